// round 7
// baseline (speedup 1.0000x reference)
#include <cuda_runtime.h>

#define NR 6144
typedef unsigned long long ull;

// ------------------------- scratch (device globals) -------------------------
__device__ float g_fe [2][NR*64];
__device__ float g_cs [2][64];
__device__ float g_x  [2][NR*64];
__device__ float g_q  [2][NR*64];
__device__ float g_k  [2][NR*64];
__device__ float g_v  [2][NR*64];
__device__ float g_kvp[2][48][512];
__device__ float g_M  [2][4096];
__device__ float g_emb[2][NR*64];
__device__ float g_comb[NR*64];
__device__ float g_u  [2][NR*64];
__device__ float g_p0 [2][NR*64];
__device__ float g_p1 [2][NR*64];

// ------------------------- helpers -------------------------
__device__ __forceinline__ float spikef(float x){
    float y = 4.0f * x;
    y = fminf(fmaxf(y, 0.0f), 4.0f);
    return floorf(y + 0.5f) * 0.25f;
}
__device__ __forceinline__ ull pack2(float lo, float hi){
    ull r;
    asm("mov.b64 %0, {%1, %2};" : "=l"(r) : "r"(__float_as_uint(lo)), "r"(__float_as_uint(hi)));
    return r;
}
__device__ __forceinline__ void ffma2(ull &d, ull a, ull b){
    asm("fma.rn.f32x2 %0, %1, %2, %0;" : "+l"(d) : "l"(a), "l"(b));
}
__device__ __forceinline__ void unpack2(ull v, float &lo, float &hi){
    unsigned a, b;
    asm("mov.b64 {%0, %1}, %2;" : "=r"(a), "=r"(b) : "l"(v));
    lo = __uint_as_float(a); hi = __uint_as_float(b);
}

// ------------------------- GEMM v4: 64x64 tile, 128 thr, BK=16, dbuf -------------------------
// Lanes = row pairs; B pre-duplicated in smem -> inner loop has ZERO movs:
//   per k-step: 2x LDS.128 (A, 4 row-pairs) + 2x LDS.128 (B dup, 4 cols) + 16 FFMA2
// C[*, ldn] = post( A[*, lda restricted to K cols] @ B[K, ldn] )
struct KA {
    const float* A0;
    const float* A1;
    const float* B;
    const float* X;
    float* C;
    float* C2;
    const float* cs;
    const float* cw;
    const float* cb;
    int K;     // K extent of this (possibly split) slice
    int lda;   // row stride of A
    int ldn;   // row stride of B and C
};
struct KA6 { KA a[6]; };

#define BK 16

template<bool DUAL, bool SPIKE, bool ADDX, bool COLS, bool C2W, bool NB>
__global__ void __launch_bounds__(128, 4) gemm4(KA6 P){
    const KA a = P.a[blockIdx.z];
    const int tid = threadIdx.x;
    const int row0 = blockIdx.x * 64;
    const int n0 = NB ? blockIdx.y * 64 : 0;
    const int K = a.K;
    const int lda = a.lda;
    const int ldn = a.ldn;
    const int nt = (K + BK - 1) / BK;

    __shared__ float As[2][BK][64];   // [k][row]
    __shared__ ull   Bs[2][BK][64];   // [k][col], value duplicated in both lanes

    // loader mapping
    const int arow = tid & 63;             // 0..63
    const int ack  = (tid >> 6) * 8;       // 0 or 8
    const int bk   = tid >> 4;             // 0..7 (rows bk, bk+8)
    const int bc   = (tid & 15) * 4;       // 0..60

    const float* Ap0 = a.A0 + (size_t)(row0 + arow) * lda + ack;
    const float* Ap1 = DUAL ? (a.A1 + (size_t)(row0 + arow) * lda + ack) : (const float*)0;
    const float* Bp  = a.B + (size_t)bk * ldn + n0 + bc;

    float w0 = 1.0f, w1 = 0.0f;
    if (DUAL){ w0 = a.cw[0]; w1 = a.cw[1]; }

    // compute mapping: 8 rows x 4 cols per thread
    const int tx = tid & 7;                // rows 8*tx .. 8*tx+7
    const int ty = tid >> 3;               // cols 4*ty .. 4*ty+3

    ull acc[4][4];                         // [rowpair][col]
    #pragma unroll
    for (int i = 0; i < 4; i++)
        #pragma unroll
        for (int j = 0; j < 4; j++) acc[i][j] = 0ull;

    const bool ncol_ok = (!NB) || (n0 + bc < ldn);

    float4 ra0, ra1, qa0, qa1, rb0, rb1;
    const float4 Z = make_float4(0.f,0.f,0.f,0.f);

    // ---- prefetch tile 0 ----
    {
        ra0 = (ack < K)     ? *(const float4*)(Ap0)     : Z;
        ra1 = (ack + 4 < K) ? *(const float4*)(Ap0 + 4) : Z;
        if (DUAL){
            qa0 = (ack < K)     ? *(const float4*)(Ap1)     : Z;
            qa1 = (ack + 4 < K) ? *(const float4*)(Ap1 + 4) : Z;
        }
        rb0 = (ncol_ok && bk < K)     ? *(const float4*)(Bp)                  : Z;
        rb1 = (ncol_ok && bk + 8 < K) ? *(const float4*)(Bp + (size_t)8*ldn)  : Z;
    }
    // ---- store tile 0 ----
    {
        float x0=ra0.x, x1=ra0.y, x2=ra0.z, x3=ra0.w;
        float y0=ra1.x, y1=ra1.y, y2=ra1.z, y3=ra1.w;
        if (DUAL){
            x0=w0*x0+w1*qa0.x; x1=w0*x1+w1*qa0.y; x2=w0*x2+w1*qa0.z; x3=w0*x3+w1*qa0.w;
            y0=w0*y0+w1*qa1.x; y1=w0*y1+w1*qa1.y; y2=w0*y2+w1*qa1.z; y3=w0*y3+w1*qa1.w;
        }
        As[0][ack+0][arow]=x0; As[0][ack+1][arow]=x1; As[0][ack+2][arow]=x2; As[0][ack+3][arow]=x3;
        As[0][ack+4][arow]=y0; As[0][ack+5][arow]=y1; As[0][ack+6][arow]=y2; As[0][ack+7][arow]=y3;
        Bs[0][bk][bc+0]=pack2(rb0.x,rb0.x); Bs[0][bk][bc+1]=pack2(rb0.y,rb0.y);
        Bs[0][bk][bc+2]=pack2(rb0.z,rb0.z); Bs[0][bk][bc+3]=pack2(rb0.w,rb0.w);
        Bs[0][bk+8][bc+0]=pack2(rb1.x,rb1.x); Bs[0][bk+8][bc+1]=pack2(rb1.y,rb1.y);
        Bs[0][bk+8][bc+2]=pack2(rb1.z,rb1.z); Bs[0][bk+8][bc+3]=pack2(rb1.w,rb1.w);
    }
    __syncthreads();

    for (int t = 0; t < nt; t++){
        if (t + 1 < nt){
            const int k0 = (t + 1) * BK;
            ra0 = (k0 + ack < K)     ? *(const float4*)(Ap0 + k0)     : Z;
            ra1 = (k0 + ack + 4 < K) ? *(const float4*)(Ap0 + k0 + 4) : Z;
            if (DUAL){
                qa0 = (k0 + ack < K)     ? *(const float4*)(Ap1 + k0)     : Z;
                qa1 = (k0 + ack + 4 < K) ? *(const float4*)(Ap1 + k0 + 4) : Z;
            }
            rb0 = (ncol_ok && k0 + bk < K)     ? *(const float4*)(Bp + (size_t)k0*ldn)     : Z;
            rb1 = (ncol_ok && k0 + bk + 8 < K) ? *(const float4*)(Bp + (size_t)(k0+8)*ldn) : Z;
        }
        const int buf = t & 1;
        #pragma unroll
        for (int k = 0; k < BK; k++){
            ulonglong2 a01 = *(const ulonglong2*)&As[buf][k][tx*8];
            ulonglong2 a23 = *(const ulonglong2*)&As[buf][k][tx*8+4];
            ulonglong2 b01 = *(const ulonglong2*)&Bs[buf][k][ty*4];
            ulonglong2 b23 = *(const ulonglong2*)&Bs[buf][k][ty*4+2];
            ffma2(acc[0][0], a01.x, b01.x); ffma2(acc[0][1], a01.x, b01.y);
            ffma2(acc[0][2], a01.x, b23.x); ffma2(acc[0][3], a01.x, b23.y);
            ffma2(acc[1][0], a01.y, b01.x); ffma2(acc[1][1], a01.y, b01.y);
            ffma2(acc[1][2], a01.y, b23.x); ffma2(acc[1][3], a01.y, b23.y);
            ffma2(acc[2][0], a23.x, b01.x); ffma2(acc[2][1], a23.x, b01.y);
            ffma2(acc[2][2], a23.x, b23.x); ffma2(acc[2][3], a23.x, b23.y);
            ffma2(acc[3][0], a23.y, b01.x); ffma2(acc[3][1], a23.y, b01.y);
            ffma2(acc[3][2], a23.y, b23.x); ffma2(acc[3][3], a23.y, b23.y);
        }
        if (t + 1 < nt){
            const int nb = (t + 1) & 1;
            float x0=ra0.x, x1=ra0.y, x2=ra0.z, x3=ra0.w;
            float y0=ra1.x, y1=ra1.y, y2=ra1.z, y3=ra1.w;
            if (DUAL){
                x0=w0*x0+w1*qa0.x; x1=w0*x1+w1*qa0.y; x2=w0*x2+w1*qa0.z; x3=w0*x3+w1*qa0.w;
                y0=w0*y0+w1*qa1.x; y1=w0*y1+w1*qa1.y; y2=w0*y2+w1*qa1.z; y3=w0*y3+w1*qa1.w;
            }
            As[nb][ack+0][arow]=x0; As[nb][ack+1][arow]=x1; As[nb][ack+2][arow]=x2; As[nb][ack+3][arow]=x3;
            As[nb][ack+4][arow]=y0; As[nb][ack+5][arow]=y1; As[nb][ack+6][arow]=y2; As[nb][ack+7][arow]=y3;
            Bs[nb][bk][bc+0]=pack2(rb0.x,rb0.x); Bs[nb][bk][bc+1]=pack2(rb0.y,rb0.y);
            Bs[nb][bk][bc+2]=pack2(rb0.z,rb0.z); Bs[nb][bk][bc+3]=pack2(rb0.w,rb0.w);
            Bs[nb][bk+8][bc+0]=pack2(rb1.x,rb1.x); Bs[nb][bk+8][bc+1]=pack2(rb1.y,rb1.y);
            Bs[nb][bk+8][bc+2]=pack2(rb1.z,rb1.z); Bs[nb][bk+8][bc+3]=pack2(rb1.w,rb1.w);
            __syncthreads();
        }
    }

    // ---- epilogue ----
    const int col = ty * 4;
    float v[8][4];
    #pragma unroll
    for (int rp = 0; rp < 4; rp++)
        #pragma unroll
        for (int c = 0; c < 4; c++)
            unpack2(acc[rp][c], v[2*rp][c], v[2*rp+1][c]);

    float cs0=0.f, cs1=0.f, cs2=0.f, cs3=0.f;
    if (COLS){
        float cb = a.cb[0];
        cs0 = cb*a.cs[col]; cs1 = cb*a.cs[col+1]; cs2 = cb*a.cs[col+2]; cs3 = cb*a.cs[col+3];
    }
    const bool colok = (!NB) || (n0 + col < ldn);
    if (colok){
        #pragma unroll
        for (int i = 0; i < 8; i++){
            int r = row0 + tx*8 + i;
            float v0=v[i][0], v1=v[i][1], v2=v[i][2], v3=v[i][3];
            if (COLS){ v0+=cs0; v1+=cs1; v2+=cs2; v3+=cs3; }
            if (ADDX){
                const float* xr = a.X + (size_t)r*64 + col;
                v0+=xr[0]; v1+=xr[1]; v2+=xr[2]; v3+=xr[3];
            }
            if (SPIKE){ v0=spikef(v0); v1=spikef(v1); v2=spikef(v2); v3=spikef(v3); }
            *(float4*)(a.C + (size_t)r*ldn + n0 + col) = make_float4(v0,v1,v2,v3);
            if (C2W)
                *(float4*)(a.C2 + (size_t)r*ldn + n0 + col) = make_float4(v0,v1,v2,v3);
        }
    }
}

// ------------------------- combine partials: dst = post(p0 + p1) -------------------------
struct CB { const float* p0; const float* p1; float* dst; const float* cs; const float* cb; };
struct CB2 { CB c[2]; };

template<bool SPIKE, bool COLS>
__global__ void __launch_bounds__(256) combine_k(CB2 P){
    const CB c = P.c[blockIdx.y];
    const int idx = (blockIdx.x * 256 + threadIdx.x) * 4;   // grid.x = 384 -> 393216 elems
    float4 a = *(const float4*)(c.p0 + idx);
    float4 b = *(const float4*)(c.p1 + idx);
    float v0 = a.x + b.x, v1 = a.y + b.y, v2 = a.z + b.z, v3 = a.w + b.w;
    if (COLS){
        int col = idx & 63;
        float4 cs4 = *(const float4*)(c.cs + col);
        float cb = c.cb[0];
        v0 += cb*cs4.x; v1 += cb*cs4.y; v2 += cb*cs4.z; v3 += cb*cs4.w;
    }
    if (SPIKE){ v0=spikef(v0); v1=spikef(v1); v2=spikef(v2); v3=spikef(v3); }
    *(float4*)(c.dst + idx) = make_float4(v0,v1,v2,v3);
}

// ------------------------- column sums of fe -------------------------
__global__ void __launch_bounds__(256) colsum_kernel(){
    int c = blockIdx.x, om = blockIdx.y;
    float s = 0.f;
    for (int r = threadIdx.x; r < NR; r += 256) s += g_fe[om][(size_t)r*64 + c];
    __shared__ float red[256];
    red[threadIdx.x] = s;
    __syncthreads();
    for (int o = 128; o > 0; o >>= 1){
        if (threadIdx.x < o) red[threadIdx.x] += red[threadIdx.x + o];
        __syncthreads();
    }
    if (threadIdx.x == 0) g_cs[om][c] = red[0];
}

// ------------------------- partial kv = sum_n k[n,h,d] v[n,h,e] -------------------------
__global__ void __launch_bounds__(512) kvpart_kernel(){
    int om = blockIdx.y, bx = blockIdx.x;
    int tid = threadIdx.x;
    int h = tid >> 6, d = (tid >> 3) & 7, e = tid & 7;
    __shared__ float ks[8][64], vs[8][64];
    int r0 = bx * 128;
    int lr = tid >> 6, lc = tid & 63;
    float acc = 0.f;
    for (int c = 0; c < 16; c++){
        ks[lr][lc] = g_k[om][(size_t)(r0 + c*8 + lr)*64 + lc];
        vs[lr][lc] = g_v[om][(size_t)(r0 + c*8 + lr)*64 + lc];
        __syncthreads();
        #pragma unroll
        for (int n = 0; n < 8; n++)
            acc += ks[n][h*8 + d] * vs[n][h*8 + e];
        __syncthreads();
    }
    g_kvp[om][bx][tid] = acc;
}

// ------------------------- reduce kv, build M[hd,c] = 0.25 * sum_e kv[h,d,e] wp[he,c] ------
__global__ void __launch_bounds__(512) kvm_kernel(const float* wp0, const float* wp1){
    int om = blockIdx.x;
    const float* wp = om ? wp1 : wp0;
    int tid = threadIdx.x;
    __shared__ float kvs[512];
    float s = 0.f;
    for (int b = 0; b < 48; b++) s += g_kvp[om][b][tid];
    kvs[tid] = s;
    __syncthreads();
    #pragma unroll
    for (int i = 0; i < 8; i++){
        int idx = tid + i*512;
        int hd = idx >> 6, c = idx & 63;
        int h = hd >> 3, dd = hd & 7;
        float m = 0.f;
        #pragma unroll
        for (int e = 0; e < 8; e++)
            m += kvs[h*64 + dd*8 + e] * wp[(h*8 + e)*64 + c];
        g_M[om][idx] = 0.25f * m;
    }
}

// ------------------------- fused MLP -------------------------
__global__ void __launch_bounds__(256) fc_kernel(const float* fc1w, const float* fc1b,
                                                 const float* fc2w, const float* fc2b,
                                                 float* out3){
    __shared__ float cat_s[64][129];
    int tid = threadIdx.x;
    int row0 = blockIdx.x * 64;
    int tx = tid & 15, ty = tid >> 4;

    for (int i = tid; i < 64*128; i += 256){
        int row = i >> 7, k = i & 127;
        float v = (k < 64) ? g_emb[0][(size_t)(row0+row)*64 + k]
                           : g_emb[1][(size_t)(row0+row)*64 + (k - 64)];
        cat_s[row][k] = v;
    }
    __syncthreads();

    float acc[4][4];
    #pragma unroll
    for (int i = 0; i < 4; i++)
        #pragma unroll
        for (int j = 0; j < 4; j++) acc[i][j] = 0.f;

    for (int k = 0; k < 128; k++){
        float aa[4], bb[4];
        #pragma unroll
        for (int i = 0; i < 4; i++) aa[i] = cat_s[tx*4 + i][k];
        #pragma unroll
        for (int j = 0; j < 4; j++) bb[j] = fc1w[k*64 + ty*4 + j];
        #pragma unroll
        for (int i = 0; i < 4; i++)
            #pragma unroll
            for (int j = 0; j < 4; j++) acc[i][j] += aa[i]*bb[j];
    }
    __syncthreads();
    #pragma unroll
    for (int i = 0; i < 4; i++)
        #pragma unroll
        for (int j = 0; j < 4; j++)
            cat_s[tx*4 + i][ty*4 + j] = spikef(acc[i][j] + fc1b[ty*4 + j]);
    __syncthreads();

    float acc2[4][4];
    #pragma unroll
    for (int i = 0; i < 4; i++)
        #pragma unroll
        for (int j = 0; j < 4; j++) acc2[i][j] = 0.f;
    for (int k = 0; k < 64; k++){
        float aa[4], bb[4];
        #pragma unroll
        for (int i = 0; i < 4; i++) aa[i] = cat_s[tx*4 + i][k];
        #pragma unroll
        for (int j = 0; j < 4; j++) bb[j] = fc2w[k*64 + ty*4 + j];
        #pragma unroll
        for (int i = 0; i < 4; i++)
            #pragma unroll
            for (int j = 0; j < 4; j++) acc2[i][j] += aa[i]*bb[j];
    }
    #pragma unroll
    for (int i = 0; i < 4; i++)
        #pragma unroll
        for (int j = 0; j < 4; j++){
            int r = row0 + tx*4 + i, c = ty*4 + j;
            float v = acc2[i][j] + fc2b[c];
            g_comb[(size_t)r*64 + c] = v;
            out3[(size_t)r*64 + c]   = spikef(v);
        }
}

// ------------------------- launch -------------------------
static inline KA mkKA(const float* A0, const float* A1, const float* B, const float* X,
                      float* C, float* C2, const float* cs, const float* cw,
                      const float* cb, int K, int lda, int ldn){
    KA a; a.A0=A0; a.A1=A1; a.B=B; a.X=X; a.C=C; a.C2=C2;
    a.cs=cs; a.cw=cw; a.cb=cb; a.K=K; a.lda=lda; a.ldn=ldn; return a;
}

extern "C" void kernel_launch(void* const* d_in, const int* in_sizes, int n_in,
                              void* d_out, int out_size){
    const float* feat1 = (const float*)d_in[0];
    const float* feat2 = (const float*)d_in[1];
    const float* AS1   = (const float*)d_in[2];
    const float* AF1   = (const float*)d_in[3];
    const float* AS2   = (const float*)d_in[4];
    const float* AF2   = (const float*)d_in[5];
    const float* c1w   = (const float*)d_in[6];
    const float* c1b   = (const float*)d_in[7];
    const float* c2w   = (const float*)d_in[8];
    const float* c2b   = (const float*)d_in[9];
    const float* wenc1 = (const float*)d_in[10];
    const float* wq1   = (const float*)d_in[11];
    const float* wk1   = (const float*)d_in[12];
    const float* wv1   = (const float*)d_in[13];
    const float* wp1   = (const float*)d_in[14];
    const float* wenc2 = (const float*)d_in[15];
    const float* wq2   = (const float*)d_in[16];
    const float* wk2   = (const float*)d_in[17];
    const float* wv2   = (const float*)d_in[18];
    const float* wp2   = (const float*)d_in[19];
    const float* fc1w  = (const float*)d_in[20];
    const float* fc1b  = (const float*)d_in[21];
    const float* fc2w  = (const float*)d_in[22];
    const float* fc2b  = (const float*)d_in[23];
    const float* wdec1 = (const float*)d_in[24];
    const float* wdec2 = (const float*)d_in[25];
    float* out = (float*)d_out;

    float *p_fe, *p_cs, *p_x, *p_q, *p_k, *p_v, *p_M, *p_emb, *p_comb, *p_u, *p_0, *p_1;
    cudaGetSymbolAddress((void**)&p_fe,  g_fe);
    cudaGetSymbolAddress((void**)&p_cs,  g_cs);
    cudaGetSymbolAddress((void**)&p_x,   g_x);
    cudaGetSymbolAddress((void**)&p_q,   g_q);
    cudaGetSymbolAddress((void**)&p_k,   g_k);
    cudaGetSymbolAddress((void**)&p_v,   g_v);
    cudaGetSymbolAddress((void**)&p_M,   g_M);
    cudaGetSymbolAddress((void**)&p_emb, g_emb);
    cudaGetSymbolAddress((void**)&p_comb,g_comb);
    cudaGetSymbolAddress((void**)&p_u,   g_u);
    cudaGetSymbolAddress((void**)&p_0,   g_p0);
    cudaGetSymbolAddress((void**)&p_1,   g_p1);
    const int OFF = NR*64;

    KA6 P;
    CB2 C2;

    // 1. fe partials: feat @ w_enc, K-split x2  (z = omics*2 + split)
    P.a[0] = mkKA(feat1,        0, wenc1,          0, p_0,       0, 0,0,0, 1500, 3000, 64);
    P.a[1] = mkKA(feat1 + 1500, 0, wenc1 + 1500*64,0, p_1,       0, 0,0,0, 1500, 3000, 64);
    P.a[2] = mkKA(feat2,        0, wenc2,          0, p_0 + OFF, 0, 0,0,0, 256,  512,  64);
    P.a[3] = mkKA(feat2 + 256,  0, wenc2 + 256*64, 0, p_1 + OFF, 0, 0,0,0, 256,  512,  64);
    P.a[4] = P.a[0]; P.a[5] = P.a[0];
    gemm4<false,false,false,false,false,false><<<dim3(96,1,4), 128>>>(P);

    // combine -> g_fe
    C2.c[0] = CB{p_0,       p_1,       p_fe,       0, 0};
    C2.c[1] = CB{p_0 + OFF, p_1 + OFF, p_fe + OFF, 0, 0};
    combine_k<false,false><<<dim3(384,2), 256>>>(C2);

    // 2. column sums of fe
    colsum_kernel<<<dim3(64, 2), 256>>>();

    // 3. x partials: (w0*AS + w1*AF) @ fe, K-split x2
    P.a[0] = mkKA(AS1,        AF1,        p_fe,               0, p_0,       0, 0, c1w, 0, 3072, NR, 64);
    P.a[1] = mkKA(AS1 + 3072, AF1 + 3072, p_fe + 3072*64,     0, p_1,       0, 0, c1w, 0, 3072, NR, 64);
    P.a[2] = mkKA(AS2,        AF2,        p_fe + OFF,         0, p_0 + OFF, 0, 0, c2w, 0, 3072, NR, 64);
    P.a[3] = mkKA(AS2 + 3072, AF2 + 3072, p_fe + OFF + 3072*64,0,p_1 + OFF, 0, 0, c2w, 0, 3072, NR, 64);
    P.a[4] = P.a[0]; P.a[5] = P.a[0];
    gemm4<true,false,false,false,false,false><<<dim3(96,1,4), 128>>>(P);

    // combine -> x = spike(p0 + p1 + cb*colsum)
    C2.c[0] = CB{p_0,       p_1,       p_x,       p_cs,      c1b};
    C2.c[1] = CB{p_0 + OFF, p_1 + OFF, p_x + OFF, p_cs + 64, c2b};
    combine_k<true,true><<<dim3(384,2), 256>>>(C2);

    // 4. q,k,v = spike(x @ w)  — six GEMMs in one launch
    P.a[0] = mkKA(p_x,       0, wq1, 0, p_q,       0, 0,0,0, 64, 64, 64);
    P.a[1] = mkKA(p_x + OFF, 0, wq2, 0, p_q + OFF, 0, 0,0,0, 64, 64, 64);
    P.a[2] = mkKA(p_x,       0, wk1, 0, p_k,       0, 0,0,0, 64, 64, 64);
    P.a[3] = mkKA(p_x + OFF, 0, wk2, 0, p_k + OFF, 0, 0,0,0, 64, 64, 64);
    P.a[4] = mkKA(p_x,       0, wv1, 0, p_v,       0, 0,0,0, 64, 64, 64);
    P.a[5] = mkKA(p_x + OFF, 0, wv2, 0, p_v + OFF, 0, 0,0,0, 64, 64, 64);
    gemm4<false,true,false,false,false,false><<<dim3(96,1,6), 128>>>(P);

    // 5-6. kv partials, reduce + fold wp into M
    kvpart_kernel<<<dim3(48, 2), 512>>>();
    kvm_kernel<<<2, 512>>>(wp1, wp2);

    // 7. emb = x + q @ M   (writes g_emb and emb1/emb2 output regions)
    P.a[0] = mkKA(p_q,       0, p_M,        p_x,       p_emb,       out,       0,0,0, 64, 64, 64);
    P.a[1] = mkKA(p_q + OFF, 0, p_M + 4096, p_x + OFF, p_emb + OFF, out + OFF, 0,0,0, 64, 64, 64);
    P.a[2] = P.a[0]; P.a[3] = P.a[0]; P.a[4] = P.a[0]; P.a[5] = P.a[0];
    gemm4<false,false,true,false,true,false><<<dim3(96,1,2), 128>>>(P);

    // 8. MLP
    fc_kernel<<<96, 256>>>(fc1w, fc1b, fc2w, fc2b, out + 2*OFF);

    // 9. u partials: AS @ comb, K-split x2
    P.a[0] = mkKA(AS1,        0, p_comb,           0, p_0,       0, 0,0,0, 3072, NR, 64);
    P.a[1] = mkKA(AS1 + 3072, 0, p_comb + 3072*64, 0, p_1,       0, 0,0,0, 3072, NR, 64);
    P.a[2] = mkKA(AS2,        0, p_comb,           0, p_0 + OFF, 0, 0,0,0, 3072, NR, 64);
    P.a[3] = mkKA(AS2 + 3072, 0, p_comb + 3072*64, 0, p_1 + OFF, 0, 0,0,0, 3072, NR, 64);
    P.a[4] = P.a[0]; P.a[5] = P.a[0];
    gemm4<false,false,false,false,false,false><<<dim3(96,1,4), 128>>>(P);

    // combine -> g_u
    C2.c[0] = CB{p_0,       p_1,       p_u,       0, 0};
    C2.c[1] = CB{p_0 + OFF, p_1 + OFF, p_u + OFF, 0, 0};
    combine_k<false,false><<<dim3(384,2), 256>>>(C2);

    // 10. recon = spike(u @ w_dec)  (N-tiled)
    P.a[0] = mkKA(p_u, 0, wdec1, 0, out + 3*(size_t)OFF, 0, 0,0,0, 64, 64, 3000);
    for (int i = 1; i < 6; i++) P.a[i] = P.a[0];
    gemm4<false,true,false,false,false,true><<<dim3(96,47,1), 128>>>(P);

    P.a[0] = mkKA(p_u + OFF, 0, wdec2, 0, out + 3*(size_t)OFF + (size_t)NR*3000,
                  0, 0,0,0, 64, 64, 512);
    for (int i = 1; i < 6; i++) P.a[i] = P.a[0];
    gemm4<false,true,false,false,false,true><<<dim3(96,8,1), 128>>>(P);
}

// round 8
// speedup vs baseline: 1.2965x; 1.2965x over previous
#include <cuda_runtime.h>

#define NR 6144
typedef unsigned long long ull;

// ------------------------- scratch (device globals) -------------------------
__device__ float g_fe [2][NR*64];
__device__ float g_cs [2][64];
__device__ float g_x  [2][NR*64];
__device__ float g_q  [2][NR*64];
__device__ float g_k  [2][NR*64];
__device__ float g_v  [2][NR*64];
__device__ float g_kvp[2][48][512];
__device__ float g_M  [2][4096];
__device__ float g_emb[2][NR*64];
__device__ float g_comb[NR*64];
__device__ float g_u  [2][NR*64];
__device__ float g_p  [4][2][NR*64];   // K-split partials

// ------------------------- helpers -------------------------
__device__ __forceinline__ float spikef(float x){
    float y = 4.0f * x;
    y = fminf(fmaxf(y, 0.0f), 4.0f);
    return floorf(y + 0.5f) * 0.25f;
}
__device__ __forceinline__ ull pack2(float lo, float hi){
    ull r;
    asm("mov.b64 %0, {%1, %2};" : "=l"(r) : "r"(__float_as_uint(lo)), "r"(__float_as_uint(hi)));
    return r;
}
__device__ __forceinline__ void ffma2(ull &d, ull a, ull b){
    asm("fma.rn.f32x2 %0, %1, %2, %0;" : "+l"(d) : "l"(a), "l"(b));
}
__device__ __forceinline__ void unpack2(ull v, float &lo, float &hi){
    unsigned a, b;
    asm("mov.b64 {%0, %1}, %2;" : "=r"(a), "=r"(b) : "l"(v));
    lo = __uint_as_float(a); hi = __uint_as_float(b);
}

// ------------------------- GEMM v5: 32x64 tile, 128 thr, BK=16, dbuf, B-dup smem ----------
// Inner loop per k-step: 1 LDS.128 (A rowpairs) + 2 LDS.128 (B dup) + 8 FFMA2 -> fma-bound.
// A slice: rows [row0..row0+32), k in [0..K) of a matrix with row stride lda
// (caller offsets A/B pointers for K-splits). B row stride = ldn = C row stride.
struct KA {
    const float* A0;
    const float* A1;
    const float* B;
    const float* X;
    float* C;
    float* C2;
    const float* cw;
    int K;
    int lda;
    int ldn;
};
struct KA8 { KA a[8]; };

#define BK 16

template<bool DUAL, bool SPIKE, bool ADDX, bool C2W, bool NB>
__global__ void __launch_bounds__(128, 6) gemm5(KA8 P){
    const KA a = P.a[blockIdx.z];
    const int tid = threadIdx.x;
    const int row0 = blockIdx.x * 32;
    const int n0 = NB ? blockIdx.y * 64 : 0;
    const int K = a.K;
    const int lda = a.lda;
    const int ldn = a.ldn;
    const int nt = (K + BK - 1) / BK;

    __shared__ float As[2][BK][36];   // [k][row]
    __shared__ ull   Bs[2][BK][64];   // [k][col] duplicated

    // loader mapping
    const int arow = tid >> 2;             // 0..31
    const int akq  = (tid & 3) * 4;        // 0,4,8,12
    const int bk   = tid >> 4;             // 0..7 (rows bk, bk+8)
    const int bc   = (tid & 15) * 4;       // 0..60

    const float* Ap0 = a.A0 + (size_t)(row0 + arow) * lda + akq;
    const float* Ap1 = DUAL ? (a.A1 + (size_t)(row0 + arow) * lda + akq) : (const float*)0;
    const float* Bp  = a.B + (size_t)bk * ldn + n0 + bc;

    float w0 = 1.0f, w1 = 0.0f;
    if (DUAL){ w0 = a.cw[0]; w1 = a.cw[1]; }

    // compute mapping: 4 rows x 4 cols per thread
    const int tx = tid & 7;                // rows 4*tx..4*tx+3
    const int ty = tid >> 3;               // cols 4*ty..4*ty+3

    ull acc[2][4];                         // [rowpair][col]
    #pragma unroll
    for (int i = 0; i < 2; i++)
        #pragma unroll
        for (int j = 0; j < 4; j++) acc[i][j] = 0ull;

    const bool ncol_ok = (!NB) || (n0 + bc < ldn);
    const float4 Z = make_float4(0.f,0.f,0.f,0.f);
    float4 ra, qa, rb0, rb1;

    // ---- prefetch + store tile 0 ----
    ra = (akq < K) ? *(const float4*)(Ap0) : Z;
    qa = Z;
    if (DUAL && akq < K) qa = *(const float4*)(Ap1);
    rb0 = (ncol_ok && bk < K)     ? *(const float4*)(Bp)                 : Z;
    rb1 = (ncol_ok && bk + 8 < K) ? *(const float4*)(Bp + (size_t)8*ldn) : Z;
    {
        float x0=ra.x, x1=ra.y, x2=ra.z, x3=ra.w;
        if (DUAL){ x0=w0*x0+w1*qa.x; x1=w0*x1+w1*qa.y; x2=w0*x2+w1*qa.z; x3=w0*x3+w1*qa.w; }
        As[0][akq+0][arow]=x0; As[0][akq+1][arow]=x1;
        As[0][akq+2][arow]=x2; As[0][akq+3][arow]=x3;
        Bs[0][bk][bc+0]=pack2(rb0.x,rb0.x); Bs[0][bk][bc+1]=pack2(rb0.y,rb0.y);
        Bs[0][bk][bc+2]=pack2(rb0.z,rb0.z); Bs[0][bk][bc+3]=pack2(rb0.w,rb0.w);
        Bs[0][bk+8][bc+0]=pack2(rb1.x,rb1.x); Bs[0][bk+8][bc+1]=pack2(rb1.y,rb1.y);
        Bs[0][bk+8][bc+2]=pack2(rb1.z,rb1.z); Bs[0][bk+8][bc+3]=pack2(rb1.w,rb1.w);
    }
    __syncthreads();

    for (int t = 0; t < nt; t++){
        if (t + 1 < nt){
            const int k0 = (t + 1) * BK;
            ra = (k0 + akq < K) ? *(const float4*)(Ap0 + k0) : Z;
            if (DUAL) qa = (k0 + akq < K) ? *(const float4*)(Ap1 + k0) : Z;
            rb0 = (ncol_ok && k0 + bk < K)     ? *(const float4*)(Bp + (size_t)k0*ldn)     : Z;
            rb1 = (ncol_ok && k0 + bk + 8 < K) ? *(const float4*)(Bp + (size_t)(k0+8)*ldn) : Z;
        }
        const int buf = t & 1;
        #pragma unroll
        for (int k = 0; k < BK; k++){
            ulonglong2 aa  = *(const ulonglong2*)&As[buf][k][tx*4];
            ulonglong2 b01 = *(const ulonglong2*)&Bs[buf][k][ty*4];
            ulonglong2 b23 = *(const ulonglong2*)&Bs[buf][k][ty*4+2];
            ffma2(acc[0][0], aa.x, b01.x); ffma2(acc[0][1], aa.x, b01.y);
            ffma2(acc[0][2], aa.x, b23.x); ffma2(acc[0][3], aa.x, b23.y);
            ffma2(acc[1][0], aa.y, b01.x); ffma2(acc[1][1], aa.y, b01.y);
            ffma2(acc[1][2], aa.y, b23.x); ffma2(acc[1][3], aa.y, b23.y);
        }
        if (t + 1 < nt){
            const int nb = (t + 1) & 1;
            float x0=ra.x, x1=ra.y, x2=ra.z, x3=ra.w;
            if (DUAL){ x0=w0*x0+w1*qa.x; x1=w0*x1+w1*qa.y; x2=w0*x2+w1*qa.z; x3=w0*x3+w1*qa.w; }
            As[nb][akq+0][arow]=x0; As[nb][akq+1][arow]=x1;
            As[nb][akq+2][arow]=x2; As[nb][akq+3][arow]=x3;
            Bs[nb][bk][bc+0]=pack2(rb0.x,rb0.x); Bs[nb][bk][bc+1]=pack2(rb0.y,rb0.y);
            Bs[nb][bk][bc+2]=pack2(rb0.z,rb0.z); Bs[nb][bk][bc+3]=pack2(rb0.w,rb0.w);
            Bs[nb][bk+8][bc+0]=pack2(rb1.x,rb1.x); Bs[nb][bk+8][bc+1]=pack2(rb1.y,rb1.y);
            Bs[nb][bk+8][bc+2]=pack2(rb1.z,rb1.z); Bs[nb][bk+8][bc+3]=pack2(rb1.w,rb1.w);
            __syncthreads();
        }
    }

    // ---- epilogue ----
    const int col = ty * 4;
    const bool colok = (!NB) || (n0 + col < ldn);
    if (colok){
        float v[4][4];
        #pragma unroll
        for (int c = 0; c < 4; c++){
            unpack2(acc[0][c], v[0][c], v[1][c]);
            unpack2(acc[1][c], v[2][c], v[3][c]);
        }
        #pragma unroll
        for (int i = 0; i < 4; i++){
            int r = row0 + tx*4 + i;
            float v0=v[i][0], v1=v[i][1], v2=v[i][2], v3=v[i][3];
            if (ADDX){
                const float* xr = a.X + (size_t)r*64 + col;
                v0+=xr[0]; v1+=xr[1]; v2+=xr[2]; v3+=xr[3];
            }
            if (SPIKE){ v0=spikef(v0); v1=spikef(v1); v2=spikef(v2); v3=spikef(v3); }
            *(float4*)(a.C + (size_t)r*ldn + n0 + col) = make_float4(v0,v1,v2,v3);
            if (C2W)
                *(float4*)(a.C2 + (size_t)r*ldn + n0 + col) = make_float4(v0,v1,v2,v3);
        }
    }
}

// ------------------------- combine 4 partials: dst = post(p0+p1+p2+p3) -------------------------
struct CB { const float* p0; const float* p1; const float* p2; const float* p3;
            float* dst; const float* cs; const float* cb; };
struct CB2 { CB c[2]; };

template<bool SPIKE, bool COLS>
__global__ void __launch_bounds__(256) combine4(CB2 P){
    const CB c = P.c[blockIdx.y];
    const int idx = (blockIdx.x * 256 + threadIdx.x) * 4;   // grid.x=384 covers NR*64
    float4 a = *(const float4*)(c.p0 + idx);
    float4 b = *(const float4*)(c.p1 + idx);
    float4 d = *(const float4*)(c.p2 + idx);
    float4 e = *(const float4*)(c.p3 + idx);
    float v0 = (a.x + b.x) + (d.x + e.x);
    float v1 = (a.y + b.y) + (d.y + e.y);
    float v2 = (a.z + b.z) + (d.z + e.z);
    float v3 = (a.w + b.w) + (d.w + e.w);
    if (COLS){
        int col = idx & 63;
        float4 cs4 = *(const float4*)(c.cs + col);
        float cb = c.cb[0];
        v0 += cb*cs4.x; v1 += cb*cs4.y; v2 += cb*cs4.z; v3 += cb*cs4.w;
    }
    if (SPIKE){ v0=spikef(v0); v1=spikef(v1); v2=spikef(v2); v3=spikef(v3); }
    *(float4*)(c.dst + idx) = make_float4(v0,v1,v2,v3);
}

// ------------------------- column sums of fe -------------------------
__global__ void __launch_bounds__(256) colsum_kernel(){
    int c = blockIdx.x, om = blockIdx.y;
    float s = 0.f;
    for (int r = threadIdx.x; r < NR; r += 256) s += g_fe[om][(size_t)r*64 + c];
    __shared__ float red[256];
    red[threadIdx.x] = s;
    __syncthreads();
    for (int o = 128; o > 0; o >>= 1){
        if (threadIdx.x < o) red[threadIdx.x] += red[threadIdx.x + o];
        __syncthreads();
    }
    if (threadIdx.x == 0) g_cs[om][c] = red[0];
}

// ------------------------- partial kv = sum_n k[n,h,d] v[n,h,e] -------------------------
__global__ void __launch_bounds__(512) kvpart_kernel(){
    int om = blockIdx.y, bx = blockIdx.x;
    int tid = threadIdx.x;
    int h = tid >> 6, d = (tid >> 3) & 7, e = tid & 7;
    __shared__ float ks[8][64], vs[8][64];
    int r0 = bx * 128;
    int lr = tid >> 6, lc = tid & 63;
    float acc = 0.f;
    for (int c = 0; c < 16; c++){
        ks[lr][lc] = g_k[om][(size_t)(r0 + c*8 + lr)*64 + lc];
        vs[lr][lc] = g_v[om][(size_t)(r0 + c*8 + lr)*64 + lc];
        __syncthreads();
        #pragma unroll
        for (int n = 0; n < 8; n++)
            acc += ks[n][h*8 + d] * vs[n][h*8 + e];
        __syncthreads();
    }
    g_kvp[om][bx][tid] = acc;
}

// ------------------------- reduce kv, build M[hd,c] -------------------------
__global__ void __launch_bounds__(512) kvm_kernel(const float* wp0, const float* wp1){
    int om = blockIdx.x;
    const float* wp = om ? wp1 : wp0;
    int tid = threadIdx.x;
    __shared__ float kvs[512];
    float s = 0.f;
    for (int b = 0; b < 48; b++) s += g_kvp[om][b][tid];
    kvs[tid] = s;
    __syncthreads();
    #pragma unroll
    for (int i = 0; i < 8; i++){
        int idx = tid + i*512;
        int hd = idx >> 6, c = idx & 63;
        int h = hd >> 3, dd = hd & 7;
        float m = 0.f;
        #pragma unroll
        for (int e = 0; e < 8; e++)
            m += kvs[h*64 + dd*8 + e] * wp[(h*8 + e)*64 + c];
        g_M[om][idx] = 0.25f * m;
    }
}

// ------------------------- fused MLP -------------------------
__global__ void __launch_bounds__(256) fc_kernel(const float* fc1w, const float* fc1b,
                                                 const float* fc2w, const float* fc2b,
                                                 float* out3){
    __shared__ float cat_s[64][129];
    int tid = threadIdx.x;
    int row0 = blockIdx.x * 64;
    int tx = tid & 15, ty = tid >> 4;

    for (int i = tid; i < 64*128; i += 256){
        int row = i >> 7, k = i & 127;
        float v = (k < 64) ? g_emb[0][(size_t)(row0+row)*64 + k]
                           : g_emb[1][(size_t)(row0+row)*64 + (k - 64)];
        cat_s[row][k] = v;
    }
    __syncthreads();

    float acc[4][4];
    #pragma unroll
    for (int i = 0; i < 4; i++)
        #pragma unroll
        for (int j = 0; j < 4; j++) acc[i][j] = 0.f;

    for (int k = 0; k < 128; k++){
        float aa[4], bb[4];
        #pragma unroll
        for (int i = 0; i < 4; i++) aa[i] = cat_s[tx*4 + i][k];
        #pragma unroll
        for (int j = 0; j < 4; j++) bb[j] = fc1w[k*64 + ty*4 + j];
        #pragma unroll
        for (int i = 0; i < 4; i++)
            #pragma unroll
            for (int j = 0; j < 4; j++) acc[i][j] += aa[i]*bb[j];
    }
    __syncthreads();
    #pragma unroll
    for (int i = 0; i < 4; i++)
        #pragma unroll
        for (int j = 0; j < 4; j++)
            cat_s[tx*4 + i][ty*4 + j] = spikef(acc[i][j] + fc1b[ty*4 + j]);
    __syncthreads();

    float acc2[4][4];
    #pragma unroll
    for (int i = 0; i < 4; i++)
        #pragma unroll
        for (int j = 0; j < 4; j++) acc2[i][j] = 0.f;
    for (int k = 0; k < 64; k++){
        float aa[4], bb[4];
        #pragma unroll
        for (int i = 0; i < 4; i++) aa[i] = cat_s[tx*4 + i][k];
        #pragma unroll
        for (int j = 0; j < 4; j++) bb[j] = fc2w[k*64 + ty*4 + j];
        #pragma unroll
        for (int i = 0; i < 4; i++)
            #pragma unroll
            for (int j = 0; j < 4; j++) acc2[i][j] += aa[i]*bb[j];
    }
    #pragma unroll
    for (int i = 0; i < 4; i++)
        #pragma unroll
        for (int j = 0; j < 4; j++){
            int r = row0 + tx*4 + i, c = ty*4 + j;
            float v = acc2[i][j] + fc2b[c];
            g_comb[(size_t)r*64 + c] = v;
            out3[(size_t)r*64 + c]   = spikef(v);
        }
}

// ------------------------- launch -------------------------
static inline KA mkKA(const float* A0, const float* A1, const float* B, const float* X,
                      float* C, float* C2, const float* cw, int K, int lda, int ldn){
    KA a; a.A0=A0; a.A1=A1; a.B=B; a.X=X; a.C=C; a.C2=C2;
    a.cw=cw; a.K=K; a.lda=lda; a.ldn=ldn; return a;
}

extern "C" void kernel_launch(void* const* d_in, const int* in_sizes, int n_in,
                              void* d_out, int out_size){
    const float* feat1 = (const float*)d_in[0];
    const float* feat2 = (const float*)d_in[1];
    const float* AS1   = (const float*)d_in[2];
    const float* AF1   = (const float*)d_in[3];
    const float* AS2   = (const float*)d_in[4];
    const float* AF2   = (const float*)d_in[5];
    const float* c1w   = (const float*)d_in[6];
    const float* c1b   = (const float*)d_in[7];
    const float* c2w   = (const float*)d_in[8];
    const float* c2b   = (const float*)d_in[9];
    const float* wenc1 = (const float*)d_in[10];
    const float* wq1   = (const float*)d_in[11];
    const float* wk1   = (const float*)d_in[12];
    const float* wv1   = (const float*)d_in[13];
    const float* wp1   = (const float*)d_in[14];
    const float* wenc2 = (const float*)d_in[15];
    const float* wq2   = (const float*)d_in[16];
    const float* wk2   = (const float*)d_in[17];
    const float* wv2   = (const float*)d_in[18];
    const float* wp2   = (const float*)d_in[19];
    const float* fc1w  = (const float*)d_in[20];
    const float* fc1b  = (const float*)d_in[21];
    const float* fc2w  = (const float*)d_in[22];
    const float* fc2b  = (const float*)d_in[23];
    const float* wdec1 = (const float*)d_in[24];
    const float* wdec2 = (const float*)d_in[25];
    float* out = (float*)d_out;

    float *p_fe, *p_cs, *p_x, *p_q, *p_k, *p_v, *p_M, *p_emb, *p_comb, *p_u, *p_p;
    cudaGetSymbolAddress((void**)&p_fe,  g_fe);
    cudaGetSymbolAddress((void**)&p_cs,  g_cs);
    cudaGetSymbolAddress((void**)&p_x,   g_x);
    cudaGetSymbolAddress((void**)&p_q,   g_q);
    cudaGetSymbolAddress((void**)&p_k,   g_k);
    cudaGetSymbolAddress((void**)&p_v,   g_v);
    cudaGetSymbolAddress((void**)&p_M,   g_M);
    cudaGetSymbolAddress((void**)&p_emb, g_emb);
    cudaGetSymbolAddress((void**)&p_comb,g_comb);
    cudaGetSymbolAddress((void**)&p_u,   g_u);
    cudaGetSymbolAddress((void**)&p_p,   g_p);
    const int OFF = NR*64;
    #define PP(s, om) (p_p + ((s)*2 + (om))*(size_t)OFF)

    KA8 P;
    CB2 C2;

    // 1. fe partials: feat @ w_enc, K-split x4  (z = om*4 + s)
    {
        const int off1[5] = {0, 768, 1536, 2304, 3000};
        const int off2[5] = {0, 128, 256, 384, 512};
        for (int s = 0; s < 4; s++){
            P.a[s]     = mkKA(feat1 + off1[s], 0, wenc1 + off1[s]*64, 0, PP(s,0), 0, 0,
                              off1[s+1]-off1[s], 3000, 64);
            P.a[4 + s] = mkKA(feat2 + off2[s], 0, wenc2 + off2[s]*64, 0, PP(s,1), 0, 0,
                              off2[s+1]-off2[s], 512, 64);
        }
        gemm5<false,false,false,false,false><<<dim3(192,1,8), 128>>>(P);
    }
    C2.c[0] = CB{PP(0,0), PP(1,0), PP(2,0), PP(3,0), p_fe,       0, 0};
    C2.c[1] = CB{PP(0,1), PP(1,1), PP(2,1), PP(3,1), p_fe + OFF, 0, 0};
    combine4<false,false><<<dim3(384,2), 256>>>(C2);

    // 2. column sums of fe
    colsum_kernel<<<dim3(64, 2), 256>>>();

    // 3. x partials: (w0*AS + w1*AF) @ fe, K-split x4
    for (int s = 0; s < 4; s++){
        int k0 = s * 1536;
        P.a[s]     = mkKA(AS1 + k0, AF1 + k0, p_fe + k0*64,       0, PP(s,0), 0, c1w, 1536, NR, 64);
        P.a[4 + s] = mkKA(AS2 + k0, AF2 + k0, p_fe + OFF + k0*64, 0, PP(s,1), 0, c2w, 1536, NR, 64);
    }
    gemm5<true,false,false,false,false><<<dim3(192,1,8), 128>>>(P);

    C2.c[0] = CB{PP(0,0), PP(1,0), PP(2,0), PP(3,0), p_x,       p_cs,      c1b};
    C2.c[1] = CB{PP(0,1), PP(1,1), PP(2,1), PP(3,1), p_x + OFF, p_cs + 64, c2b};
    combine4<true,true><<<dim3(384,2), 256>>>(C2);

    // 4. q,k,v = spike(x @ w)  — six GEMMs in one launch
    P.a[0] = mkKA(p_x,       0, wq1, 0, p_q,       0, 0, 64, 64, 64);
    P.a[1] = mkKA(p_x + OFF, 0, wq2, 0, p_q + OFF, 0, 0, 64, 64, 64);
    P.a[2] = mkKA(p_x,       0, wk1, 0, p_k,       0, 0, 64, 64, 64);
    P.a[3] = mkKA(p_x + OFF, 0, wk2, 0, p_k + OFF, 0, 0, 64, 64, 64);
    P.a[4] = mkKA(p_x,       0, wv1, 0, p_v,       0, 0, 64, 64, 64);
    P.a[5] = mkKA(p_x + OFF, 0, wv2, 0, p_v + OFF, 0, 0, 64, 64, 64);
    P.a[6] = P.a[0]; P.a[7] = P.a[0];
    gemm5<false,true,false,false,false><<<dim3(192,1,6), 128>>>(P);

    // 5-6. kv partials, reduce + fold wp into M
    kvpart_kernel<<<dim3(48, 2), 512>>>();
    kvm_kernel<<<2, 512>>>(wp1, wp2);

    // 7. emb = x + q @ M   (writes g_emb and emb1/emb2 output regions)
    P.a[0] = mkKA(p_q,       0, p_M,        p_x,       p_emb,       out,       0, 64, 64, 64);
    P.a[1] = mkKA(p_q + OFF, 0, p_M + 4096, p_x + OFF, p_emb + OFF, out + OFF, 0, 64, 64, 64);
    for (int i = 2; i < 8; i++) P.a[i] = P.a[0];
    gemm5<false,false,true,true,false><<<dim3(192,1,2), 128>>>(P);

    // 8. MLP
    fc_kernel<<<96, 256>>>(fc1w, fc1b, fc2w, fc2b, out + 2*OFF);

    // 9. u partials: AS @ comb, K-split x4
    for (int s = 0; s < 4; s++){
        int k0 = s * 1536;
        P.a[s]     = mkKA(AS1 + k0, 0, p_comb + k0*64, 0, PP(s,0), 0, 0, 1536, NR, 64);
        P.a[4 + s] = mkKA(AS2 + k0, 0, p_comb + k0*64, 0, PP(s,1), 0, 0, 1536, NR, 64);
    }
    gemm5<false,false,false,false,false><<<dim3(192,1,8), 128>>>(P);

    C2.c[0] = CB{PP(0,0), PP(1,0), PP(2,0), PP(3,0), p_u,       0, 0};
    C2.c[1] = CB{PP(0,1), PP(1,1), PP(2,1), PP(3,1), p_u + OFF, 0, 0};
    combine4<false,false><<<dim3(384,2), 256>>>(C2);

    // 10. recon = spike(u @ w_dec)  (N-tiled)
    P.a[0] = mkKA(p_u, 0, wdec1, 0, out + 3*(size_t)OFF, 0, 0, 64, 64, 3000);
    for (int i = 1; i < 8; i++) P.a[i] = P.a[0];
    gemm5<false,true,false,false,true><<<dim3(192,47,1), 128>>>(P);

    P.a[0] = mkKA(p_u + OFF, 0, wdec2, 0, out + 3*(size_t)OFF + (size_t)NR*3000,
                  0, 0, 64, 64, 512);
    for (int i = 1; i < 8; i++) P.a[i] = P.a[0];
    gemm5<false,true,false,false,true><<<dim3(192,8,1), 128>>>(P);
}

// round 9
// speedup vs baseline: 1.4167x; 1.0927x over previous
#include <cuda_runtime.h>

#define NR 6144
typedef unsigned long long ull;

// ------------------------- scratch (device globals) -------------------------
__device__ float g_fe [2][NR*64];
__device__ float g_cs [2][64];
__device__ float g_x  [2][NR*64];
__device__ float g_q  [2][NR*64];
__device__ float g_k  [2][NR*64];
__device__ float g_v  [2][NR*64];
__device__ float g_kvp[2][48][512];
__device__ float g_M  [2][4096];
__device__ float g_emb[2][NR*64];
__device__ float g_comb[NR*64];
__device__ float g_u  [2][NR*64];
__device__ float g_p  [4][2][NR*64];   // K-split partials

// ------------------------- helpers -------------------------
__device__ __forceinline__ float spikef(float x){
    float y = 4.0f * x;
    y = fminf(fmaxf(y, 0.0f), 4.0f);
    return floorf(y + 0.5f) * 0.25f;
}
__device__ __forceinline__ ull pack2(float lo, float hi){
    ull r;
    asm("mov.b64 %0, {%1, %2};" : "=l"(r) : "r"(__float_as_uint(lo)), "r"(__float_as_uint(hi)));
    return r;
}
__device__ __forceinline__ void ffma2(ull &d, ull a, ull b){
    asm("fma.rn.f32x2 %0, %1, %2, %0;" : "+l"(d) : "l"(a), "l"(b));
}
__device__ __forceinline__ void unpack2(ull v, float &lo, float &hi){
    unsigned a, b;
    asm("mov.b64 {%0, %1}, %2;" : "=r"(a), "=r"(b) : "l"(v));
    lo = __uint_as_float(a); hi = __uint_as_float(b);
}

// ------------------------- GEMM v6: 128x64 tile, 128 thr, 8x8/thread, BK=8, dbuf ----------
// Crossbar math: per k-step/thread 6 LDS.128 = 96B for 64 lane-FMA (1.5 B/FMA) vs
// balance point 1 B/FMA -> ~67% fma ceiling (was 3 B/FMA -> 33%).
// Requires K % 8 == 0 (true for all call sites: 752/744/128/1536/64).
struct KA {
    const float* A0;
    const float* A1;
    const float* B;
    const float* X;
    float* C;
    float* C2;
    const float* cw;
    int K;
    int lda;
    int ldn;
};
struct KA8 { KA a[8]; };

#define BK 8
#define MT 128

template<bool DUAL, bool SPIKE, bool ADDX, bool C2W, bool NB>
__global__ void __launch_bounds__(128, 3) gemm6(KA8 P){
    const KA a = P.a[blockIdx.z];
    const int tid = threadIdx.x;
    const int row0 = blockIdx.x * MT;
    const int n0 = NB ? blockIdx.y * 64 : 0;
    const int K = a.K;
    const int lda = a.lda;
    const int ldn = a.ldn;
    const int nt = K / BK;

    __shared__ float As[2][BK][MT];   // [k][row]
    __shared__ ull   Bs[2][BK][64];   // [k][col] duplicated in both lanes

    // loader mapping: A -> one row per thread, k 0..7 contiguous
    const int arow = tid;
    const int bk   = tid >> 4;             // 0..7
    const int bc   = (tid & 15) * 4;       // 0..60

    const float* Ap0 = a.A0 + (size_t)(row0 + arow) * lda;
    const float* Ap1 = DUAL ? (a.A1 + (size_t)(row0 + arow) * lda) : (const float*)0;
    const float* Bp  = a.B + (size_t)bk * ldn + n0 + bc;

    float w0 = 1.0f, w1 = 0.0f;
    if (DUAL){ w0 = a.cw[0]; w1 = a.cw[1]; }

    // compute mapping: 8 rows x 8 cols per thread
    const int tx = tid & 15;               // rows 8*tx .. 8*tx+7
    const int ty = tid >> 4;               // cols 8*ty .. 8*ty+7

    ull acc[4][8];                         // [rowpair][col]
    #pragma unroll
    for (int i = 0; i < 4; i++)
        #pragma unroll
        for (int j = 0; j < 8; j++) acc[i][j] = 0ull;

    const bool ncol_ok = (!NB) || (n0 + bc + 4 <= ldn);
    const float4 Z = make_float4(0.f,0.f,0.f,0.f);
    float4 ra0, ra1, qa0, qa1, rb;

    // ---- prefetch + stage tile 0 ----
    ra0 = *(const float4*)(Ap0);
    ra1 = *(const float4*)(Ap0 + 4);
    if (DUAL){ qa0 = *(const float4*)(Ap1); qa1 = *(const float4*)(Ap1 + 4); }
    rb  = ncol_ok ? *(const float4*)(Bp) : Z;
    {
        float x0=ra0.x, x1=ra0.y, x2=ra0.z, x3=ra0.w;
        float y0=ra1.x, y1=ra1.y, y2=ra1.z, y3=ra1.w;
        if (DUAL){
            x0=w0*x0+w1*qa0.x; x1=w0*x1+w1*qa0.y; x2=w0*x2+w1*qa0.z; x3=w0*x3+w1*qa0.w;
            y0=w0*y0+w1*qa1.x; y1=w0*y1+w1*qa1.y; y2=w0*y2+w1*qa1.z; y3=w0*y3+w1*qa1.w;
        }
        As[0][0][arow]=x0; As[0][1][arow]=x1; As[0][2][arow]=x2; As[0][3][arow]=x3;
        As[0][4][arow]=y0; As[0][5][arow]=y1; As[0][6][arow]=y2; As[0][7][arow]=y3;
        Bs[0][bk][bc+0]=pack2(rb.x,rb.x); Bs[0][bk][bc+1]=pack2(rb.y,rb.y);
        Bs[0][bk][bc+2]=pack2(rb.z,rb.z); Bs[0][bk][bc+3]=pack2(rb.w,rb.w);
    }
    __syncthreads();

    for (int t = 0; t < nt; t++){
        if (t + 1 < nt){
            const int k0 = (t + 1) * BK;
            ra0 = *(const float4*)(Ap0 + k0);
            ra1 = *(const float4*)(Ap0 + k0 + 4);
            if (DUAL){ qa0 = *(const float4*)(Ap1 + k0); qa1 = *(const float4*)(Ap1 + k0 + 4); }
            rb  = ncol_ok ? *(const float4*)(Bp + (size_t)k0*ldn) : Z;
        }
        const int buf = t & 1;
        #pragma unroll
        for (int k = 0; k < BK; k++){
            ulonglong2 a01 = *(const ulonglong2*)&As[buf][k][tx*8];
            ulonglong2 a23 = *(const ulonglong2*)&As[buf][k][tx*8+4];
            ulonglong2 b01 = *(const ulonglong2*)&Bs[buf][k][ty*8];
            ulonglong2 b23 = *(const ulonglong2*)&Bs[buf][k][ty*8+2];
            ulonglong2 b45 = *(const ulonglong2*)&Bs[buf][k][ty*8+4];
            ulonglong2 b67 = *(const ulonglong2*)&Bs[buf][k][ty*8+6];
            ffma2(acc[0][0], a01.x, b01.x); ffma2(acc[0][1], a01.x, b01.y);
            ffma2(acc[0][2], a01.x, b23.x); ffma2(acc[0][3], a01.x, b23.y);
            ffma2(acc[0][4], a01.x, b45.x); ffma2(acc[0][5], a01.x, b45.y);
            ffma2(acc[0][6], a01.x, b67.x); ffma2(acc[0][7], a01.x, b67.y);
            ffma2(acc[1][0], a01.y, b01.x); ffma2(acc[1][1], a01.y, b01.y);
            ffma2(acc[1][2], a01.y, b23.x); ffma2(acc[1][3], a01.y, b23.y);
            ffma2(acc[1][4], a01.y, b45.x); ffma2(acc[1][5], a01.y, b45.y);
            ffma2(acc[1][6], a01.y, b67.x); ffma2(acc[1][7], a01.y, b67.y);
            ffma2(acc[2][0], a23.x, b01.x); ffma2(acc[2][1], a23.x, b01.y);
            ffma2(acc[2][2], a23.x, b23.x); ffma2(acc[2][3], a23.x, b23.y);
            ffma2(acc[2][4], a23.x, b45.x); ffma2(acc[2][5], a23.x, b45.y);
            ffma2(acc[2][6], a23.x, b67.x); ffma2(acc[2][7], a23.x, b67.y);
            ffma2(acc[3][0], a23.y, b01.x); ffma2(acc[3][1], a23.y, b01.y);
            ffma2(acc[3][2], a23.y, b23.x); ffma2(acc[3][3], a23.y, b23.y);
            ffma2(acc[3][4], a23.y, b45.x); ffma2(acc[3][5], a23.y, b45.y);
            ffma2(acc[3][6], a23.y, b67.x); ffma2(acc[3][7], a23.y, b67.y);
        }
        if (t + 1 < nt){
            const int nb = (t + 1) & 1;
            float x0=ra0.x, x1=ra0.y, x2=ra0.z, x3=ra0.w;
            float y0=ra1.x, y1=ra1.y, y2=ra1.z, y3=ra1.w;
            if (DUAL){
                x0=w0*x0+w1*qa0.x; x1=w0*x1+w1*qa0.y; x2=w0*x2+w1*qa0.z; x3=w0*x3+w1*qa0.w;
                y0=w0*y0+w1*qa1.x; y1=w0*y1+w1*qa1.y; y2=w0*y2+w1*qa1.z; y3=w0*y3+w1*qa1.w;
            }
            As[nb][0][arow]=x0; As[nb][1][arow]=x1; As[nb][2][arow]=x2; As[nb][3][arow]=x3;
            As[nb][4][arow]=y0; As[nb][5][arow]=y1; As[nb][6][arow]=y2; As[nb][7][arow]=y3;
            Bs[nb][bk][bc+0]=pack2(rb.x,rb.x); Bs[nb][bk][bc+1]=pack2(rb.y,rb.y);
            Bs[nb][bk][bc+2]=pack2(rb.z,rb.z); Bs[nb][bk][bc+3]=pack2(rb.w,rb.w);
            __syncthreads();
        }
    }

    // ---- epilogue ----
    const int col = n0 + ty * 8;
    const bool ok0 = (!NB) || (col + 4 <= ldn);
    const bool ok1 = (!NB) || (col + 8 <= ldn);
    #pragma unroll
    for (int rp = 0; rp < 4; rp++){
        float v0[8], v1[8];
        #pragma unroll
        for (int c = 0; c < 8; c++) unpack2(acc[rp][c], v0[c], v1[c]);
        #pragma unroll
        for (int half = 0; half < 2; half++){
            float* vv = half ? v1 : v0;
            int r = row0 + tx*8 + rp*2 + half;
            if (ADDX){
                const float* xr = a.X + (size_t)r*64 + ty*8;
                #pragma unroll
                for (int c = 0; c < 8; c++) vv[c] += xr[c];
            }
            if (SPIKE){
                #pragma unroll
                for (int c = 0; c < 8; c++) vv[c] = spikef(vv[c]);
            }
            if (ok0)
                *(float4*)(a.C + (size_t)r*ldn + col) = make_float4(vv[0],vv[1],vv[2],vv[3]);
            if (ok1)
                *(float4*)(a.C + (size_t)r*ldn + col + 4) = make_float4(vv[4],vv[5],vv[6],vv[7]);
            if (C2W){
                if (ok0)
                    *(float4*)(a.C2 + (size_t)r*ldn + col) = make_float4(vv[0],vv[1],vv[2],vv[3]);
                if (ok1)
                    *(float4*)(a.C2 + (size_t)r*ldn + col + 4) = make_float4(vv[4],vv[5],vv[6],vv[7]);
            }
        }
    }
}

// ------------------------- combine 4 partials -------------------------
struct CB { const float* p0; const float* p1; const float* p2; const float* p3;
            float* dst; const float* cs; const float* cb; };
struct CB2 { CB c[2]; };

template<bool SPIKE, bool COLS>
__global__ void __launch_bounds__(256) combine4(CB2 P){
    const CB c = P.c[blockIdx.y];
    const int idx = (blockIdx.x * 256 + threadIdx.x) * 4;
    float4 a = *(const float4*)(c.p0 + idx);
    float4 b = *(const float4*)(c.p1 + idx);
    float4 d = *(const float4*)(c.p2 + idx);
    float4 e = *(const float4*)(c.p3 + idx);
    float v0 = (a.x + b.x) + (d.x + e.x);
    float v1 = (a.y + b.y) + (d.y + e.y);
    float v2 = (a.z + b.z) + (d.z + e.z);
    float v3 = (a.w + b.w) + (d.w + e.w);
    if (COLS){
        int col = idx & 63;
        float4 cs4 = *(const float4*)(c.cs + col);
        float cb = c.cb[0];
        v0 += cb*cs4.x; v1 += cb*cs4.y; v2 += cb*cs4.z; v3 += cb*cs4.w;
    }
    if (SPIKE){ v0=spikef(v0); v1=spikef(v1); v2=spikef(v2); v3=spikef(v3); }
    *(float4*)(c.dst + idx) = make_float4(v0,v1,v2,v3);
}

// ------------------------- column sums of fe -------------------------
__global__ void __launch_bounds__(256) colsum_kernel(){
    int c = blockIdx.x, om = blockIdx.y;
    float s = 0.f;
    for (int r = threadIdx.x; r < NR; r += 256) s += g_fe[om][(size_t)r*64 + c];
    __shared__ float red[256];
    red[threadIdx.x] = s;
    __syncthreads();
    for (int o = 128; o > 0; o >>= 1){
        if (threadIdx.x < o) red[threadIdx.x] += red[threadIdx.x + o];
        __syncthreads();
    }
    if (threadIdx.x == 0) g_cs[om][c] = red[0];
}

// ------------------------- partial kv -------------------------
__global__ void __launch_bounds__(512) kvpart_kernel(){
    int om = blockIdx.y, bx = blockIdx.x;
    int tid = threadIdx.x;
    int h = tid >> 6, d = (tid >> 3) & 7, e = tid & 7;
    __shared__ float ks[8][64], vs[8][64];
    int r0 = bx * 128;
    int lr = tid >> 6, lc = tid & 63;
    float acc = 0.f;
    for (int c = 0; c < 16; c++){
        ks[lr][lc] = g_k[om][(size_t)(r0 + c*8 + lr)*64 + lc];
        vs[lr][lc] = g_v[om][(size_t)(r0 + c*8 + lr)*64 + lc];
        __syncthreads();
        #pragma unroll
        for (int n = 0; n < 8; n++)
            acc += ks[n][h*8 + d] * vs[n][h*8 + e];
        __syncthreads();
    }
    g_kvp[om][bx][tid] = acc;
}

// ------------------------- reduce kv, build M -------------------------
__global__ void __launch_bounds__(512) kvm_kernel(const float* wp0, const float* wp1){
    int om = blockIdx.x;
    const float* wp = om ? wp1 : wp0;
    int tid = threadIdx.x;
    __shared__ float kvs[512];
    float s = 0.f;
    for (int b = 0; b < 48; b++) s += g_kvp[om][b][tid];
    kvs[tid] = s;
    __syncthreads();
    #pragma unroll
    for (int i = 0; i < 8; i++){
        int idx = tid + i*512;
        int hd = idx >> 6, c = idx & 63;
        int h = hd >> 3, dd = hd & 7;
        float m = 0.f;
        #pragma unroll
        for (int e = 0; e < 8; e++)
            m += kvs[h*64 + dd*8 + e] * wp[(h*8 + e)*64 + c];
        g_M[om][idx] = 0.25f * m;
    }
}

// ------------------------- fused MLP -------------------------
__global__ void __launch_bounds__(256) fc_kernel(const float* fc1w, const float* fc1b,
                                                 const float* fc2w, const float* fc2b,
                                                 float* out3){
    __shared__ float cat_s[64][129];
    int tid = threadIdx.x;
    int row0 = blockIdx.x * 64;
    int tx = tid & 15, ty = tid >> 4;

    for (int i = tid; i < 64*128; i += 256){
        int row = i >> 7, k = i & 127;
        float v = (k < 64) ? g_emb[0][(size_t)(row0+row)*64 + k]
                           : g_emb[1][(size_t)(row0+row)*64 + (k - 64)];
        cat_s[row][k] = v;
    }
    __syncthreads();

    float acc[4][4];
    #pragma unroll
    for (int i = 0; i < 4; i++)
        #pragma unroll
        for (int j = 0; j < 4; j++) acc[i][j] = 0.f;

    for (int k = 0; k < 128; k++){
        float aa[4], bb[4];
        #pragma unroll
        for (int i = 0; i < 4; i++) aa[i] = cat_s[tx*4 + i][k];
        #pragma unroll
        for (int j = 0; j < 4; j++) bb[j] = fc1w[k*64 + ty*4 + j];
        #pragma unroll
        for (int i = 0; i < 4; i++)
            #pragma unroll
            for (int j = 0; j < 4; j++) acc[i][j] += aa[i]*bb[j];
    }
    __syncthreads();
    #pragma unroll
    for (int i = 0; i < 4; i++)
        #pragma unroll
        for (int j = 0; j < 4; j++)
            cat_s[tx*4 + i][ty*4 + j] = spikef(acc[i][j] + fc1b[ty*4 + j]);
    __syncthreads();

    float acc2[4][4];
    #pragma unroll
    for (int i = 0; i < 4; i++)
        #pragma unroll
        for (int j = 0; j < 4; j++) acc2[i][j] = 0.f;
    for (int k = 0; k < 64; k++){
        float aa[4], bb[4];
        #pragma unroll
        for (int i = 0; i < 4; i++) aa[i] = cat_s[tx*4 + i][k];
        #pragma unroll
        for (int j = 0; j < 4; j++) bb[j] = fc2w[k*64 + ty*4 + j];
        #pragma unroll
        for (int i = 0; i < 4; i++)
            #pragma unroll
            for (int j = 0; j < 4; j++) acc2[i][j] += aa[i]*bb[j];
    }
    #pragma unroll
    for (int i = 0; i < 4; i++)
        #pragma unroll
        for (int j = 0; j < 4; j++){
            int r = row0 + tx*4 + i, c = ty*4 + j;
            float v = acc2[i][j] + fc2b[c];
            g_comb[(size_t)r*64 + c] = v;
            out3[(size_t)r*64 + c]   = spikef(v);
        }
}

// ------------------------- launch -------------------------
static inline KA mkKA(const float* A0, const float* A1, const float* B, const float* X,
                      float* C, float* C2, const float* cw, int K, int lda, int ldn){
    KA a; a.A0=A0; a.A1=A1; a.B=B; a.X=X; a.C=C; a.C2=C2;
    a.cw=cw; a.K=K; a.lda=lda; a.ldn=ldn; return a;
}

extern "C" void kernel_launch(void* const* d_in, const int* in_sizes, int n_in,
                              void* d_out, int out_size){
    const float* feat1 = (const float*)d_in[0];
    const float* feat2 = (const float*)d_in[1];
    const float* AS1   = (const float*)d_in[2];
    const float* AF1   = (const float*)d_in[3];
    const float* AS2   = (const float*)d_in[4];
    const float* AF2   = (const float*)d_in[5];
    const float* c1w   = (const float*)d_in[6];
    const float* c1b   = (const float*)d_in[7];
    const float* c2w   = (const float*)d_in[8];
    const float* c2b   = (const float*)d_in[9];
    const float* wenc1 = (const float*)d_in[10];
    const float* wq1   = (const float*)d_in[11];
    const float* wk1   = (const float*)d_in[12];
    const float* wv1   = (const float*)d_in[13];
    const float* wp1   = (const float*)d_in[14];
    const float* wenc2 = (const float*)d_in[15];
    const float* wq2   = (const float*)d_in[16];
    const float* wk2   = (const float*)d_in[17];
    const float* wv2   = (const float*)d_in[18];
    const float* wp2   = (const float*)d_in[19];
    const float* fc1w  = (const float*)d_in[20];
    const float* fc1b  = (const float*)d_in[21];
    const float* fc2w  = (const float*)d_in[22];
    const float* fc2b  = (const float*)d_in[23];
    const float* wdec1 = (const float*)d_in[24];
    const float* wdec2 = (const float*)d_in[25];
    float* out = (float*)d_out;

    float *p_fe, *p_cs, *p_x, *p_q, *p_k, *p_v, *p_M, *p_emb, *p_comb, *p_u, *p_p;
    cudaGetSymbolAddress((void**)&p_fe,  g_fe);
    cudaGetSymbolAddress((void**)&p_cs,  g_cs);
    cudaGetSymbolAddress((void**)&p_x,   g_x);
    cudaGetSymbolAddress((void**)&p_q,   g_q);
    cudaGetSymbolAddress((void**)&p_k,   g_k);
    cudaGetSymbolAddress((void**)&p_v,   g_v);
    cudaGetSymbolAddress((void**)&p_M,   g_M);
    cudaGetSymbolAddress((void**)&p_emb, g_emb);
    cudaGetSymbolAddress((void**)&p_comb,g_comb);
    cudaGetSymbolAddress((void**)&p_u,   g_u);
    cudaGetSymbolAddress((void**)&p_p,   g_p);
    const int OFF = NR*64;
    #define PP(s, om) (p_p + ((s)*2 + (om))*(size_t)OFF)

    KA8 P;
    CB2 C2;

    // 1. fe partials: feat @ w_enc, K-split x4 (all splits divisible by 8)
    {
        const int off1[5] = {0, 752, 1504, 2256, 3000};
        const int off2[5] = {0, 128, 256, 384, 512};
        for (int s = 0; s < 4; s++){
            P.a[s]     = mkKA(feat1 + off1[s], 0, wenc1 + off1[s]*64, 0, PP(s,0), 0, 0,
                              off1[s+1]-off1[s], 3000, 64);
            P.a[4 + s] = mkKA(feat2 + off2[s], 0, wenc2 + off2[s]*64, 0, PP(s,1), 0, 0,
                              off2[s+1]-off2[s], 512, 64);
        }
        gemm6<false,false,false,false,false><<<dim3(48,1,8), 128>>>(P);
    }
    C2.c[0] = CB{PP(0,0), PP(1,0), PP(2,0), PP(3,0), p_fe,       0, 0};
    C2.c[1] = CB{PP(0,1), PP(1,1), PP(2,1), PP(3,1), p_fe + OFF, 0, 0};
    combine4<false,false><<<dim3(384,2), 256>>>(C2);

    // 2. column sums of fe
    colsum_kernel<<<dim3(64, 2), 256>>>();

    // 3. x partials: (w0*AS + w1*AF) @ fe, K-split x4
    for (int s = 0; s < 4; s++){
        int k0 = s * 1536;
        P.a[s]     = mkKA(AS1 + k0, AF1 + k0, p_fe + k0*64,       0, PP(s,0), 0, c1w, 1536, NR, 64);
        P.a[4 + s] = mkKA(AS2 + k0, AF2 + k0, p_fe + OFF + k0*64, 0, PP(s,1), 0, c2w, 1536, NR, 64);
    }
    gemm6<true,false,false,false,false><<<dim3(48,1,8), 128>>>(P);

    C2.c[0] = CB{PP(0,0), PP(1,0), PP(2,0), PP(3,0), p_x,       p_cs,      c1b};
    C2.c[1] = CB{PP(0,1), PP(1,1), PP(2,1), PP(3,1), p_x + OFF, p_cs + 64, c2b};
    combine4<true,true><<<dim3(384,2), 256>>>(C2);

    // 4. q,k,v = spike(x @ w) — six GEMMs, one launch
    P.a[0] = mkKA(p_x,       0, wq1, 0, p_q,       0, 0, 64, 64, 64);
    P.a[1] = mkKA(p_x + OFF, 0, wq2, 0, p_q + OFF, 0, 0, 64, 64, 64);
    P.a[2] = mkKA(p_x,       0, wk1, 0, p_k,       0, 0, 64, 64, 64);
    P.a[3] = mkKA(p_x + OFF, 0, wk2, 0, p_k + OFF, 0, 0, 64, 64, 64);
    P.a[4] = mkKA(p_x,       0, wv1, 0, p_v,       0, 0, 64, 64, 64);
    P.a[5] = mkKA(p_x + OFF, 0, wv2, 0, p_v + OFF, 0, 0, 64, 64, 64);
    P.a[6] = P.a[0]; P.a[7] = P.a[0];
    gemm6<false,true,false,false,false><<<dim3(48,1,6), 128>>>(P);

    // 5-6. kv partials, reduce + fold wp into M
    kvpart_kernel<<<dim3(48, 2), 512>>>();
    kvm_kernel<<<2, 512>>>(wp1, wp2);

    // 7. emb = x + q @ M  (writes g_emb and emb1/emb2 outputs)
    P.a[0] = mkKA(p_q,       0, p_M,        p_x,       p_emb,       out,       0, 64, 64, 64);
    P.a[1] = mkKA(p_q + OFF, 0, p_M + 4096, p_x + OFF, p_emb + OFF, out + OFF, 0, 64, 64, 64);
    for (int i = 2; i < 8; i++) P.a[i] = P.a[0];
    gemm6<false,false,true,true,false><<<dim3(48,1,2), 128>>>(P);

    // 8. MLP
    fc_kernel<<<96, 256>>>(fc1w, fc1b, fc2w, fc2b, out + 2*OFF);

    // 9. u partials: AS @ comb, K-split x4
    for (int s = 0; s < 4; s++){
        int k0 = s * 1536;
        P.a[s]     = mkKA(AS1 + k0, 0, p_comb + k0*64, 0, PP(s,0), 0, 0, 1536, NR, 64);
        P.a[4 + s] = mkKA(AS2 + k0, 0, p_comb + k0*64, 0, PP(s,1), 0, 0, 1536, NR, 64);
    }
    gemm6<false,false,false,false,false><<<dim3(48,1,8), 128>>>(P);

    C2.c[0] = CB{PP(0,0), PP(1,0), PP(2,0), PP(3,0), p_u,       0, 0};
    C2.c[1] = CB{PP(0,1), PP(1,1), PP(2,1), PP(3,1), p_u + OFF, 0, 0};
    combine4<false,false><<<dim3(384,2), 256>>>(C2);

    // 10. recon = spike(u @ w_dec) (N-tiled)
    P.a[0] = mkKA(p_u, 0, wdec1, 0, out + 3*(size_t)OFF, 0, 0, 64, 64, 3000);
    for (int i = 1; i < 8; i++) P.a[i] = P.a[0];
    gemm6<false,true,false,false,true><<<dim3(48,47,1), 128>>>(P);

    P.a[0] = mkKA(p_u + OFF, 0, wdec2, 0, out + 3*(size_t)OFF + (size_t)NR*3000,
                  0, 0, 64, 64, 512);
    for (int i = 1; i < 8; i++) P.a[i] = P.a[0];
    gemm6<false,true,false,false,true><<<dim3(48,8,1), 128>>>(P);
}

// round 10
// speedup vs baseline: 1.7325x; 1.2230x over previous
#include <cuda_runtime.h>

#define NR 6144
typedef unsigned long long ull;

// ------------------------- scratch (device globals) -------------------------
__device__ float g_fe [2][NR*64];
__device__ float g_cs [2][64];
__device__ float g_x  [2][NR*64];
__device__ float g_q  [2][NR*64];
__device__ float g_k  [2][NR*64];
__device__ float g_v  [2][NR*64];
__device__ float g_kvp[2][48][512];
__device__ float g_M  [2][4096];
__device__ float g_emb[2][NR*64];
__device__ float g_comb[NR*64];
__device__ float g_u  [2][NR*64];
__device__ float g_p  [6][2][NR*64];   // K-split partials (x6)

// ------------------------- helpers -------------------------
__device__ __forceinline__ float spikef(float x){
    float y = 4.0f * x;
    y = fminf(fmaxf(y, 0.0f), 4.0f);
    return floorf(y + 0.5f) * 0.25f;
}
__device__ __forceinline__ ull pack2(float lo, float hi){
    ull r;
    asm("mov.b64 %0, {%1, %2};" : "=l"(r) : "r"(__float_as_uint(lo)), "r"(__float_as_uint(hi)));
    return r;
}
__device__ __forceinline__ void ffma2(ull &d, ull a, ull b){
    asm("fma.rn.f32x2 %0, %1, %2, %0;" : "+l"(d) : "l"(a), "l"(b));
}
__device__ __forceinline__ void unpack2(ull v, float &lo, float &hi){
    unsigned a, b;
    asm("mov.b64 {%0, %1}, %2;" : "=r"(a), "=r"(b) : "l"(v));
    lo = __uint_as_float(a); hi = __uint_as_float(b);
}

// ------------------------- GEMM v7: 128x64 tile, 128 thr, 8x8/thread, BK=8 ----------------
// Swizzled A smem (conflict-free LDS.128), B dup'd (broadcast reads), dbuf, 1 sync/iter.
// K must be a multiple of 8 at every call site.
struct KA {
    const float* A0;
    const float* A1;
    const float* B;
    const float* X;
    float* C;
    float* C2;
    const float* cw;
    int K;
    int lda;
    int ldn;
};
struct KA12 { KA a[12]; };

#define BK 8
#define MT 128
#define APITCH 144   // 128 rows + swizzle spill (max idx 139)

template<bool DUAL, bool SPIKE, bool ADDX, bool C2W, bool NB>
__global__ void __launch_bounds__(128, 4) gemm7(KA12 P){
    const KA a = P.a[blockIdx.z];
    const int tid = threadIdx.x;
    const int row0 = blockIdx.x * MT;
    const int n0 = NB ? blockIdx.y * 64 : 0;
    const int K = a.K;
    const int lda = a.lda;
    const int ldn = a.ldn;
    const int nt = K / BK;

    __shared__ float As[2][BK][APITCH];   // swizzled: float idx = r + (r>>5)*4
    __shared__ ull   Bs[2][BK][64];       // [k][col] dup'd in both lanes

    // loader mapping
    const int arow = tid;                       // one A row per thread
    const int aw   = tid + ((tid >> 5) << 2);   // swizzled store index
    const int bk   = tid >> 4;                  // 0..7
    const int bc   = (tid & 15) * 4;            // 0..60

    const float* Ap0 = a.A0 + (size_t)(row0 + arow) * lda;
    const float* Ap1 = DUAL ? (a.A1 + (size_t)(row0 + arow) * lda) : (const float*)0;
    const float* Bp  = a.B + (size_t)bk * ldn + n0 + bc;

    float w0 = 1.0f, w1 = 0.0f;
    if (DUAL){ w0 = a.cw[0]; w1 = a.cw[1]; }

    // compute mapping: 8 rows x 8 cols per thread
    const int tx = tid & 15;                    // rows 8*tx .. 8*tx+7
    const int ty = tid >> 4;                    // cols 8*ty .. 8*ty+7
    const int abase = tx*8 + ((tx >> 2) << 2);  // swizzled read base

    ull acc[4][8];
    #pragma unroll
    for (int i = 0; i < 4; i++)
        #pragma unroll
        for (int j = 0; j < 8; j++) acc[i][j] = 0ull;

    const bool ncol_ok = (!NB) || (n0 + bc + 4 <= ldn);
    const float4 Z = make_float4(0.f,0.f,0.f,0.f);
    float4 ra0, ra1, qa0, qa1, rb;

    // ---- prefetch + stage tile 0 ----
    ra0 = *(const float4*)(Ap0);
    ra1 = *(const float4*)(Ap0 + 4);
    if (DUAL){ qa0 = *(const float4*)(Ap1); qa1 = *(const float4*)(Ap1 + 4); }
    rb  = ncol_ok ? *(const float4*)(Bp) : Z;
    {
        float x0=ra0.x, x1=ra0.y, x2=ra0.z, x3=ra0.w;
        float y0=ra1.x, y1=ra1.y, y2=ra1.z, y3=ra1.w;
        if (DUAL){
            x0=w0*x0+w1*qa0.x; x1=w0*x1+w1*qa0.y; x2=w0*x2+w1*qa0.z; x3=w0*x3+w1*qa0.w;
            y0=w0*y0+w1*qa1.x; y1=w0*y1+w1*qa1.y; y2=w0*y2+w1*qa1.z; y3=w0*y3+w1*qa1.w;
        }
        As[0][0][aw]=x0; As[0][1][aw]=x1; As[0][2][aw]=x2; As[0][3][aw]=x3;
        As[0][4][aw]=y0; As[0][5][aw]=y1; As[0][6][aw]=y2; As[0][7][aw]=y3;
        Bs[0][bk][bc+0]=pack2(rb.x,rb.x); Bs[0][bk][bc+1]=pack2(rb.y,rb.y);
        Bs[0][bk][bc+2]=pack2(rb.z,rb.z); Bs[0][bk][bc+3]=pack2(rb.w,rb.w);
    }
    __syncthreads();

    for (int t = 0; t < nt; t++){
        if (t + 1 < nt){
            const int k0 = (t + 1) * BK;
            ra0 = *(const float4*)(Ap0 + k0);
            ra1 = *(const float4*)(Ap0 + k0 + 4);
            if (DUAL){ qa0 = *(const float4*)(Ap1 + k0); qa1 = *(const float4*)(Ap1 + k0 + 4); }
            rb  = ncol_ok ? *(const float4*)(Bp + (size_t)k0*ldn) : Z;
        }
        const int buf = t & 1;
        #pragma unroll
        for (int k = 0; k < BK; k++){
            ulonglong2 a01 = *(const ulonglong2*)&As[buf][k][abase];
            ulonglong2 a23 = *(const ulonglong2*)&As[buf][k][abase+4];
            ulonglong2 b01 = *(const ulonglong2*)&Bs[buf][k][ty*8];
            ulonglong2 b23 = *(const ulonglong2*)&Bs[buf][k][ty*8+2];
            ulonglong2 b45 = *(const ulonglong2*)&Bs[buf][k][ty*8+4];
            ulonglong2 b67 = *(const ulonglong2*)&Bs[buf][k][ty*8+6];
            ffma2(acc[0][0], a01.x, b01.x); ffma2(acc[0][1], a01.x, b01.y);
            ffma2(acc[0][2], a01.x, b23.x); ffma2(acc[0][3], a01.x, b23.y);
            ffma2(acc[0][4], a01.x, b45.x); ffma2(acc[0][5], a01.x, b45.y);
            ffma2(acc[0][6], a01.x, b67.x); ffma2(acc[0][7], a01.x, b67.y);
            ffma2(acc[1][0], a01.y, b01.x); ffma2(acc[1][1], a01.y, b01.y);
            ffma2(acc[1][2], a01.y, b23.x); ffma2(acc[1][3], a01.y, b23.y);
            ffma2(acc[1][4], a01.y, b45.x); ffma2(acc[1][5], a01.y, b45.y);
            ffma2(acc[1][6], a01.y, b67.x); ffma2(acc[1][7], a01.y, b67.y);
            ffma2(acc[2][0], a23.x, b01.x); ffma2(acc[2][1], a23.x, b01.y);
            ffma2(acc[2][2], a23.x, b23.x); ffma2(acc[2][3], a23.x, b23.y);
            ffma2(acc[2][4], a23.x, b45.x); ffma2(acc[2][5], a23.x, b45.y);
            ffma2(acc[2][6], a23.x, b67.x); ffma2(acc[2][7], a23.x, b67.y);
            ffma2(acc[3][0], a23.y, b01.x); ffma2(acc[3][1], a23.y, b01.y);
            ffma2(acc[3][2], a23.y, b23.x); ffma2(acc[3][3], a23.y, b23.y);
            ffma2(acc[3][4], a23.y, b45.x); ffma2(acc[3][5], a23.y, b45.y);
            ffma2(acc[3][6], a23.y, b67.x); ffma2(acc[3][7], a23.y, b67.y);
        }
        if (t + 1 < nt){
            const int nb = (t + 1) & 1;
            float x0=ra0.x, x1=ra0.y, x2=ra0.z, x3=ra0.w;
            float y0=ra1.x, y1=ra1.y, y2=ra1.z, y3=ra1.w;
            if (DUAL){
                x0=w0*x0+w1*qa0.x; x1=w0*x1+w1*qa0.y; x2=w0*x2+w1*qa0.z; x3=w0*x3+w1*qa0.w;
                y0=w0*y0+w1*qa1.x; y1=w0*y1+w1*qa1.y; y2=w0*y2+w1*qa1.z; y3=w0*y3+w1*qa1.w;
            }
            As[nb][0][aw]=x0; As[nb][1][aw]=x1; As[nb][2][aw]=x2; As[nb][3][aw]=x3;
            As[nb][4][aw]=y0; As[nb][5][aw]=y1; As[nb][6][aw]=y2; As[nb][7][aw]=y3;
            Bs[nb][bk][bc+0]=pack2(rb.x,rb.x); Bs[nb][bk][bc+1]=pack2(rb.y,rb.y);
            Bs[nb][bk][bc+2]=pack2(rb.z,rb.z); Bs[nb][bk][bc+3]=pack2(rb.w,rb.w);
            __syncthreads();
        }
    }

    // ---- epilogue ----
    const int col = n0 + ty * 8;
    const bool ok0 = (!NB) || (col + 4 <= ldn);
    const bool ok1 = (!NB) || (col + 8 <= ldn);
    #pragma unroll
    for (int rp = 0; rp < 4; rp++){
        float v0[8], v1[8];
        #pragma unroll
        for (int c = 0; c < 8; c++) unpack2(acc[rp][c], v0[c], v1[c]);
        #pragma unroll
        for (int half = 0; half < 2; half++){
            float* vv = half ? v1 : v0;
            int r = row0 + tx*8 + rp*2 + half;
            if (ADDX){
                float4 xa = *(const float4*)(a.X + (size_t)r*64 + ty*8);
                float4 xb = *(const float4*)(a.X + (size_t)r*64 + ty*8 + 4);
                vv[0]+=xa.x; vv[1]+=xa.y; vv[2]+=xa.z; vv[3]+=xa.w;
                vv[4]+=xb.x; vv[5]+=xb.y; vv[6]+=xb.z; vv[7]+=xb.w;
            }
            if (SPIKE){
                #pragma unroll
                for (int c = 0; c < 8; c++) vv[c] = spikef(vv[c]);
            }
            if (ok0)
                *(float4*)(a.C + (size_t)r*ldn + col) = make_float4(vv[0],vv[1],vv[2],vv[3]);
            if (ok1)
                *(float4*)(a.C + (size_t)r*ldn + col + 4) = make_float4(vv[4],vv[5],vv[6],vv[7]);
            if (C2W){
                if (ok0)
                    *(float4*)(a.C2 + (size_t)r*ldn + col) = make_float4(vv[0],vv[1],vv[2],vv[3]);
                if (ok1)
                    *(float4*)(a.C2 + (size_t)r*ldn + col + 4) = make_float4(vv[4],vv[5],vv[6],vv[7]);
            }
        }
    }
}

// ------------------------- combine 6 partials -------------------------
struct CB { const float* p[6]; float* dst; const float* cs; const float* cb; };
struct CB2 { CB c[2]; };

template<bool SPIKE, bool COLS>
__global__ void __launch_bounds__(256) combine6(CB2 P){
    const CB c = P.c[blockIdx.y];
    const int idx = (blockIdx.x * 256 + threadIdx.x) * 4;
    float v0 = 0.f, v1 = 0.f, v2 = 0.f, v3 = 0.f;
    #pragma unroll
    for (int s = 0; s < 6; s++){
        float4 a = *(const float4*)(c.p[s] + idx);
        v0 += a.x; v1 += a.y; v2 += a.z; v3 += a.w;
    }
    if (COLS){
        int col = idx & 63;
        float4 cs4 = *(const float4*)(c.cs + col);
        float cb = c.cb[0];
        v0 += cb*cs4.x; v1 += cb*cs4.y; v2 += cb*cs4.z; v3 += cb*cs4.w;
    }
    if (SPIKE){ v0=spikef(v0); v1=spikef(v1); v2=spikef(v2); v3=spikef(v3); }
    *(float4*)(c.dst + idx) = make_float4(v0,v1,v2,v3);
}

// ------------------------- column sums of fe -------------------------
__global__ void __launch_bounds__(256) colsum_kernel(){
    int c = blockIdx.x, om = blockIdx.y;
    float s = 0.f;
    for (int r = threadIdx.x; r < NR; r += 256) s += g_fe[om][(size_t)r*64 + c];
    __shared__ float red[256];
    red[threadIdx.x] = s;
    __syncthreads();
    for (int o = 128; o > 0; o >>= 1){
        if (threadIdx.x < o) red[threadIdx.x] += red[threadIdx.x + o];
        __syncthreads();
    }
    if (threadIdx.x == 0) g_cs[om][c] = red[0];
}

// ------------------------- partial kv -------------------------
__global__ void __launch_bounds__(512) kvpart_kernel(){
    int om = blockIdx.y, bx = blockIdx.x;
    int tid = threadIdx.x;
    int h = tid >> 6, d = (tid >> 3) & 7, e = tid & 7;
    __shared__ float ks[8][64], vs[8][64];
    int r0 = bx * 128;
    int lr = tid >> 6, lc = tid & 63;
    float acc = 0.f;
    for (int c = 0; c < 16; c++){
        ks[lr][lc] = g_k[om][(size_t)(r0 + c*8 + lr)*64 + lc];
        vs[lr][lc] = g_v[om][(size_t)(r0 + c*8 + lr)*64 + lc];
        __syncthreads();
        #pragma unroll
        for (int n = 0; n < 8; n++)
            acc += ks[n][h*8 + d] * vs[n][h*8 + e];
        __syncthreads();
    }
    g_kvp[om][bx][tid] = acc;
}

// ------------------------- reduce kv, build M -------------------------
__global__ void __launch_bounds__(512) kvm_kernel(const float* wp0, const float* wp1){
    int om = blockIdx.x;
    const float* wp = om ? wp1 : wp0;
    int tid = threadIdx.x;
    __shared__ float kvs[512];
    float s = 0.f;
    for (int b = 0; b < 48; b++) s += g_kvp[om][b][tid];
    kvs[tid] = s;
    __syncthreads();
    #pragma unroll
    for (int i = 0; i < 8; i++){
        int idx = tid + i*512;
        int hd = idx >> 6, c = idx & 63;
        int h = hd >> 3, dd = hd & 7;
        float m = 0.f;
        #pragma unroll
        for (int e = 0; e < 8; e++)
            m += kvs[h*64 + dd*8 + e] * wp[(h*8 + e)*64 + c];
        g_M[om][idx] = 0.25f * m;
    }
}

// ------------------------- fused MLP -------------------------
__global__ void __launch_bounds__(256) fc_kernel(const float* fc1w, const float* fc1b,
                                                 const float* fc2w, const float* fc2b,
                                                 float* out3){
    __shared__ float cat_s[64][129];
    int tid = threadIdx.x;
    int row0 = blockIdx.x * 64;
    int tx = tid & 15, ty = tid >> 4;

    for (int i = tid; i < 64*128; i += 256){
        int row = i >> 7, k = i & 127;
        float v = (k < 64) ? g_emb[0][(size_t)(row0+row)*64 + k]
                           : g_emb[1][(size_t)(row0+row)*64 + (k - 64)];
        cat_s[row][k] = v;
    }
    __syncthreads();

    float acc[4][4];
    #pragma unroll
    for (int i = 0; i < 4; i++)
        #pragma unroll
        for (int j = 0; j < 4; j++) acc[i][j] = 0.f;

    for (int k = 0; k < 128; k++){
        float aa[4], bb[4];
        #pragma unroll
        for (int i = 0; i < 4; i++) aa[i] = cat_s[tx*4 + i][k];
        #pragma unroll
        for (int j = 0; j < 4; j++) bb[j] = fc1w[k*64 + ty*4 + j];
        #pragma unroll
        for (int i = 0; i < 4; i++)
            #pragma unroll
            for (int j = 0; j < 4; j++) acc[i][j] += aa[i]*bb[j];
    }
    __syncthreads();
    #pragma unroll
    for (int i = 0; i < 4; i++)
        #pragma unroll
        for (int j = 0; j < 4; j++)
            cat_s[tx*4 + i][ty*4 + j] = spikef(acc[i][j] + fc1b[ty*4 + j]);
    __syncthreads();

    float acc2[4][4];
    #pragma unroll
    for (int i = 0; i < 4; i++)
        #pragma unroll
        for (int j = 0; j < 4; j++) acc2[i][j] = 0.f;
    for (int k = 0; k < 64; k++){
        float aa[4], bb[4];
        #pragma unroll
        for (int i = 0; i < 4; i++) aa[i] = cat_s[tx*4 + i][k];
        #pragma unroll
        for (int j = 0; j < 4; j++) bb[j] = fc2w[k*64 + ty*4 + j];
        #pragma unroll
        for (int i = 0; i < 4; i++)
            #pragma unroll
            for (int j = 0; j < 4; j++) acc2[i][j] += aa[i]*bb[j];
    }
    #pragma unroll
    for (int i = 0; i < 4; i++)
        #pragma unroll
        for (int j = 0; j < 4; j++){
            int r = row0 + tx*4 + i, c = ty*4 + j;
            float v = acc2[i][j] + fc2b[c];
            g_comb[(size_t)r*64 + c] = v;
            out3[(size_t)r*64 + c]   = spikef(v);
        }
}

// ------------------------- launch -------------------------
static inline KA mkKA(const float* A0, const float* A1, const float* B, const float* X,
                      float* C, float* C2, const float* cw, int K, int lda, int ldn){
    KA a; a.A0=A0; a.A1=A1; a.B=B; a.X=X; a.C=C; a.C2=C2;
    a.cw=cw; a.K=K; a.lda=lda; a.ldn=ldn; return a;
}

extern "C" void kernel_launch(void* const* d_in, const int* in_sizes, int n_in,
                              void* d_out, int out_size){
    const float* feat1 = (const float*)d_in[0];
    const float* feat2 = (const float*)d_in[1];
    const float* AS1   = (const float*)d_in[2];
    const float* AF1   = (const float*)d_in[3];
    const float* AS2   = (const float*)d_in[4];
    const float* AF2   = (const float*)d_in[5];
    const float* c1w   = (const float*)d_in[6];
    const float* c1b   = (const float*)d_in[7];
    const float* c2w   = (const float*)d_in[8];
    const float* c2b   = (const float*)d_in[9];
    const float* wenc1 = (const float*)d_in[10];
    const float* wq1   = (const float*)d_in[11];
    const float* wk1   = (const float*)d_in[12];
    const float* wv1   = (const float*)d_in[13];
    const float* wp1   = (const float*)d_in[14];
    const float* wenc2 = (const float*)d_in[15];
    const float* wq2   = (const float*)d_in[16];
    const float* wk2   = (const float*)d_in[17];
    const float* wv2   = (const float*)d_in[18];
    const float* wp2   = (const float*)d_in[19];
    const float* fc1w  = (const float*)d_in[20];
    const float* fc1b  = (const float*)d_in[21];
    const float* fc2w  = (const float*)d_in[22];
    const float* fc2b  = (const float*)d_in[23];
    const float* wdec1 = (const float*)d_in[24];
    const float* wdec2 = (const float*)d_in[25];
    float* out = (float*)d_out;

    float *p_fe, *p_cs, *p_x, *p_q, *p_k, *p_v, *p_M, *p_emb, *p_comb, *p_u, *p_p;
    cudaGetSymbolAddress((void**)&p_fe,  g_fe);
    cudaGetSymbolAddress((void**)&p_cs,  g_cs);
    cudaGetSymbolAddress((void**)&p_x,   g_x);
    cudaGetSymbolAddress((void**)&p_q,   g_q);
    cudaGetSymbolAddress((void**)&p_k,   g_k);
    cudaGetSymbolAddress((void**)&p_v,   g_v);
    cudaGetSymbolAddress((void**)&p_M,   g_M);
    cudaGetSymbolAddress((void**)&p_emb, g_emb);
    cudaGetSymbolAddress((void**)&p_comb,g_comb);
    cudaGetSymbolAddress((void**)&p_u,   g_u);
    cudaGetSymbolAddress((void**)&p_p,   g_p);
    const int OFF = NR*64;
    #define PP(s, om) (p_p + ((s)*2 + (om))*(size_t)OFF)

    KA12 P;
    CB2 C2;

    // 1. fe partials: feat @ w_enc, K-split x6 (all slices %8==0)
    {
        const int off1[7] = {0, 504, 1008, 1512, 2016, 2520, 3000};
        const int off2[7] = {0, 88, 176, 264, 352, 440, 512};
        for (int s = 0; s < 6; s++){
            P.a[s]     = mkKA(feat1 + off1[s], 0, wenc1 + off1[s]*64, 0, PP(s,0), 0, 0,
                              off1[s+1]-off1[s], 3000, 64);
            P.a[6 + s] = mkKA(feat2 + off2[s], 0, wenc2 + off2[s]*64, 0, PP(s,1), 0, 0,
                              off2[s+1]-off2[s], 512, 64);
        }
        gemm7<false,false,false,false,false><<<dim3(48,1,12), 128>>>(P);
    }
    for (int om = 0; om < 2; om++){
        for (int s = 0; s < 6; s++) C2.c[om].p[s] = PP(s,om);
        C2.c[om].dst = p_fe + om*OFF; C2.c[om].cs = 0; C2.c[om].cb = 0;
    }
    combine6<false,false><<<dim3(384,2), 256>>>(C2);

    // 2. column sums of fe
    colsum_kernel<<<dim3(64, 2), 256>>>();

    // 3. x partials: (w0*AS + w1*AF) @ fe, K-split x6
    for (int s = 0; s < 6; s++){
        int k0 = s * 1024;
        P.a[s]     = mkKA(AS1 + k0, AF1 + k0, p_fe + k0*64,       0, PP(s,0), 0, c1w, 1024, NR, 64);
        P.a[6 + s] = mkKA(AS2 + k0, AF2 + k0, p_fe + OFF + k0*64, 0, PP(s,1), 0, c2w, 1024, NR, 64);
    }
    gemm7<true,false,false,false,false><<<dim3(48,1,12), 128>>>(P);

    for (int om = 0; om < 2; om++){
        for (int s = 0; s < 6; s++) C2.c[om].p[s] = PP(s,om);
        C2.c[om].dst = p_x + om*OFF;
        C2.c[om].cs = p_cs + om*64;
        C2.c[om].cb = om ? c2b : c1b;
    }
    combine6<true,true><<<dim3(384,2), 256>>>(C2);

    // 4. q,k,v = spike(x @ w) — six GEMMs, one launch
    P.a[0] = mkKA(p_x,       0, wq1, 0, p_q,       0, 0, 64, 64, 64);
    P.a[1] = mkKA(p_x + OFF, 0, wq2, 0, p_q + OFF, 0, 0, 64, 64, 64);
    P.a[2] = mkKA(p_x,       0, wk1, 0, p_k,       0, 0, 64, 64, 64);
    P.a[3] = mkKA(p_x + OFF, 0, wk2, 0, p_k + OFF, 0, 0, 64, 64, 64);
    P.a[4] = mkKA(p_x,       0, wv1, 0, p_v,       0, 0, 64, 64, 64);
    P.a[5] = mkKA(p_x + OFF, 0, wv2, 0, p_v + OFF, 0, 0, 64, 64, 64);
    for (int i = 6; i < 12; i++) P.a[i] = P.a[0];
    gemm7<false,true,false,false,false><<<dim3(48,1,6), 128>>>(P);

    // 5-6. kv partials, reduce + fold wp into M
    kvpart_kernel<<<dim3(48, 2), 512>>>();
    kvm_kernel<<<2, 512>>>(wp1, wp2);

    // 7. emb = x + q @ M  (writes g_emb and emb1/emb2 outputs)
    P.a[0] = mkKA(p_q,       0, p_M,        p_x,       p_emb,       out,       0, 64, 64, 64);
    P.a[1] = mkKA(p_q + OFF, 0, p_M + 4096, p_x + OFF, p_emb + OFF, out + OFF, 0, 64, 64, 64);
    for (int i = 2; i < 12; i++) P.a[i] = P.a[0];
    gemm7<false,false,true,true,false><<<dim3(48,1,2), 128>>>(P);

    // 8. MLP
    fc_kernel<<<96, 256>>>(fc1w, fc1b, fc2w, fc2b, out + 2*OFF);

    // 9. u partials: AS @ comb, K-split x6
    for (int s = 0; s < 6; s++){
        int k0 = s * 1024;
        P.a[s]     = mkKA(AS1 + k0, 0, p_comb + k0*64, 0, PP(s,0), 0, 0, 1024, NR, 64);
        P.a[6 + s] = mkKA(AS2 + k0, 0, p_comb + k0*64, 0, PP(s,1), 0, 0, 1024, NR, 64);
    }
    gemm7<false,false,false,false,false><<<dim3(48,1,12), 128>>>(P);

    for (int om = 0; om < 2; om++){
        for (int s = 0; s < 6; s++) C2.c[om].p[s] = PP(s,om);
        C2.c[om].dst = p_u + om*OFF; C2.c[om].cs = 0; C2.c[om].cb = 0;
    }
    combine6<false,false><<<dim3(384,2), 256>>>(C2);

    // 10. recon = spike(u @ w_dec) (N-tiled)
    P.a[0] = mkKA(p_u, 0, wdec1, 0, out + 3*(size_t)OFF, 0, 0, 64, 64, 3000);
    for (int i = 1; i < 12; i++) P.a[i] = P.a[0];
    gemm7<false,true,false,false,true><<<dim3(48,47,1), 128>>>(P);

    P.a[0] = mkKA(p_u + OFF, 0, wdec2, 0, out + 3*(size_t)OFF + (size_t)NR*3000,
                  0, 0, 64, 64, 512);
    for (int i = 1; i < 12; i++) P.a[i] = P.a[0];
    gemm7<false,true,false,false,true><<<dim3(48,8,1), 128>>>(P);
}

// round 11
// speedup vs baseline: 2.0977x; 1.2107x over previous
#include <cuda_runtime.h>

#define NR 6144
typedef unsigned long long ull;

// ------------------------- scratch (device globals) -------------------------
__device__ float g_fe [2][NR*64];
__device__ float g_cs [2][64];
__device__ float g_x  [2][NR*64];
__device__ float g_q  [2][NR*64];
__device__ float g_k  [2][NR*64];
__device__ float g_v  [2][NR*64];
__device__ float g_kvp[2][48][512];
__device__ float g_M  [2][4096];
__device__ float g_emb[2][NR*64];
__device__ float g_comb[NR*64];
__device__ float g_u  [2][NR*64];
__device__ float g_p  [6][2][NR*64];   // K-split partials (x6)

// ------------------------- helpers -------------------------
__device__ __forceinline__ float spikef(float x){
    float y = 4.0f * x;
    y = fminf(fmaxf(y, 0.0f), 4.0f);
    return floorf(y + 0.5f) * 0.25f;
}
__device__ __forceinline__ ull pack2(float lo, float hi){
    ull r;
    asm("mov.b64 %0, {%1, %2};" : "=l"(r) : "r"(__float_as_uint(lo)), "r"(__float_as_uint(hi)));
    return r;
}
__device__ __forceinline__ ull dup2(float x){ return pack2(x, x); }
__device__ __forceinline__ void ffma2(ull &d, ull a, ull b){
    asm("fma.rn.f32x2 %0, %1, %2, %0;" : "+l"(d) : "l"(a), "l"(b));
}
__device__ __forceinline__ void unpack2(ull v, float &lo, float &hi){
    unsigned a, b;
    asm("mov.b64 {%0, %1}, %2;" : "=r"(a), "=r"(b) : "l"(v));
    lo = __uint_as_float(a); hi = __uint_as_float(b);
}

// ------------------------- GEMM v8: 128x64 tile, 128 thr, 8x8/thread, BK=8 ----------------
// Minimum-LDS inner loop: A natural rowpairs (2x LDS.128, swizzled conflict-free) +
// B natural (2x LDS.128, broadcast) = 64B per 64 lane-FMA (1.0 B/FMA = crossbar balance).
// B dup pairs built in registers (8x pack2). K must be a multiple of 8 at every call site.
struct KA {
    const float* A0;
    const float* A1;
    const float* B;
    const float* X;
    float* C;
    float* C2;
    const float* cw;
    int K;
    int lda;
    int ldn;
};
struct KA12 { KA a[12]; };

#define BK 8
#define MT 128
#define APITCH 144   // 128 rows + swizzle spill (max idx 139)

template<bool DUAL, bool SPIKE, bool ADDX, bool C2W, bool NB>
__global__ void __launch_bounds__(128, 4) gemm8(KA12 P){
    const KA a = P.a[blockIdx.z];
    const int tid = threadIdx.x;
    const int row0 = blockIdx.x * MT;
    const int n0 = NB ? blockIdx.y * 64 : 0;
    const int K = a.K;
    const int lda = a.lda;
    const int ldn = a.ldn;
    const int nt = K / BK;

    __shared__ float As[2][BK][APITCH];   // swizzled: float idx = r + (r>>5)*4
    __shared__ float Bs[2][BK][64];       // [k][col] natural

    // loader mapping
    const int arow = tid;                       // one A row per thread
    const int aw   = tid + ((tid >> 5) << 2);   // swizzled store index
    const int bk   = tid >> 4;                  // 0..7
    const int bc   = (tid & 15) * 4;            // 0..60

    const float* Ap0 = a.A0 + (size_t)(row0 + arow) * lda;
    const float* Ap1 = DUAL ? (a.A1 + (size_t)(row0 + arow) * lda) : (const float*)0;
    const float* Bp  = a.B + (size_t)bk * ldn + n0 + bc;

    float w0 = 1.0f, w1 = 0.0f;
    if (DUAL){ w0 = a.cw[0]; w1 = a.cw[1]; }

    // compute mapping: 8 rows x 8 cols per thread
    const int tx = tid & 15;                    // rows 8*tx .. 8*tx+7
    const int ty = tid >> 4;                    // cols 8*ty .. 8*ty+7
    const int abase = tx*8 + ((tx >> 2) << 2);  // swizzled read base

    ull acc[4][8];
    #pragma unroll
    for (int i = 0; i < 4; i++)
        #pragma unroll
        for (int j = 0; j < 8; j++) acc[i][j] = 0ull;

    const bool ncol_ok = (!NB) || (n0 + bc + 4 <= ldn);
    const float4 Z = make_float4(0.f,0.f,0.f,0.f);
    float4 ra0, ra1, qa0, qa1, rb;

    // ---- prefetch + stage tile 0 ----
    ra0 = *(const float4*)(Ap0);
    ra1 = *(const float4*)(Ap0 + 4);
    if (DUAL){ qa0 = *(const float4*)(Ap1); qa1 = *(const float4*)(Ap1 + 4); }
    rb  = ncol_ok ? *(const float4*)(Bp) : Z;
    {
        float x0=ra0.x, x1=ra0.y, x2=ra0.z, x3=ra0.w;
        float y0=ra1.x, y1=ra1.y, y2=ra1.z, y3=ra1.w;
        if (DUAL){
            x0=w0*x0+w1*qa0.x; x1=w0*x1+w1*qa0.y; x2=w0*x2+w1*qa0.z; x3=w0*x3+w1*qa0.w;
            y0=w0*y0+w1*qa1.x; y1=w0*y1+w1*qa1.y; y2=w0*y2+w1*qa1.z; y3=w0*y3+w1*qa1.w;
        }
        As[0][0][aw]=x0; As[0][1][aw]=x1; As[0][2][aw]=x2; As[0][3][aw]=x3;
        As[0][4][aw]=y0; As[0][5][aw]=y1; As[0][6][aw]=y2; As[0][7][aw]=y3;
        *(float4*)&Bs[0][bk][bc] = rb;
    }
    __syncthreads();

    for (int t = 0; t < nt; t++){
        if (t + 1 < nt){
            const int k0 = (t + 1) * BK;
            ra0 = *(const float4*)(Ap0 + k0);
            ra1 = *(const float4*)(Ap0 + k0 + 4);
            if (DUAL){ qa0 = *(const float4*)(Ap1 + k0); qa1 = *(const float4*)(Ap1 + k0 + 4); }
            rb  = ncol_ok ? *(const float4*)(Bp + (size_t)k0*ldn) : Z;
        }
        const int buf = t & 1;
        #pragma unroll
        for (int k = 0; k < BK; k++){
            ulonglong2 a01 = *(const ulonglong2*)&As[buf][k][abase];
            ulonglong2 a23 = *(const ulonglong2*)&As[buf][k][abase+4];
            float4 b0 = *(const float4*)&Bs[buf][k][ty*8];
            float4 b1 = *(const float4*)&Bs[buf][k][ty*8+4];
            ull d0 = dup2(b0.x), d1 = dup2(b0.y), d2 = dup2(b0.z), d3 = dup2(b0.w);
            ull d4 = dup2(b1.x), d5 = dup2(b1.y), d6 = dup2(b1.z), d7 = dup2(b1.w);
            ffma2(acc[0][0], a01.x, d0); ffma2(acc[0][1], a01.x, d1);
            ffma2(acc[0][2], a01.x, d2); ffma2(acc[0][3], a01.x, d3);
            ffma2(acc[0][4], a01.x, d4); ffma2(acc[0][5], a01.x, d5);
            ffma2(acc[0][6], a01.x, d6); ffma2(acc[0][7], a01.x, d7);
            ffma2(acc[1][0], a01.y, d0); ffma2(acc[1][1], a01.y, d1);
            ffma2(acc[1][2], a01.y, d2); ffma2(acc[1][3], a01.y, d3);
            ffma2(acc[1][4], a01.y, d4); ffma2(acc[1][5], a01.y, d5);
            ffma2(acc[1][6], a01.y, d6); ffma2(acc[1][7], a01.y, d7);
            ffma2(acc[2][0], a23.x, d0); ffma2(acc[2][1], a23.x, d1);
            ffma2(acc[2][2], a23.x, d2); ffma2(acc[2][3], a23.x, d3);
            ffma2(acc[2][4], a23.x, d4); ffma2(acc[2][5], a23.x, d5);
            ffma2(acc[2][6], a23.x, d6); ffma2(acc[2][7], a23.x, d7);
            ffma2(acc[3][0], a23.y, d0); ffma2(acc[3][1], a23.y, d1);
            ffma2(acc[3][2], a23.y, d2); ffma2(acc[3][3], a23.y, d3);
            ffma2(acc[3][4], a23.y, d4); ffma2(acc[3][5], a23.y, d5);
            ffma2(acc[3][6], a23.y, d6); ffma2(acc[3][7], a23.y, d7);
        }
        if (t + 1 < nt){
            const int nb = (t + 1) & 1;
            float x0=ra0.x, x1=ra0.y, x2=ra0.z, x3=ra0.w;
            float y0=ra1.x, y1=ra1.y, y2=ra1.z, y3=ra1.w;
            if (DUAL){
                x0=w0*x0+w1*qa0.x; x1=w0*x1+w1*qa0.y; x2=w0*x2+w1*qa0.z; x3=w0*x3+w1*qa0.w;
                y0=w0*y0+w1*qa1.x; y1=w0*y1+w1*qa1.y; y2=w0*y2+w1*qa1.z; y3=w0*y3+w1*qa1.w;
            }
            As[nb][0][aw]=x0; As[nb][1][aw]=x1; As[nb][2][aw]=x2; As[nb][3][aw]=x3;
            As[nb][4][aw]=y0; As[nb][5][aw]=y1; As[nb][6][aw]=y2; As[nb][7][aw]=y3;
            *(float4*)&Bs[nb][bk][bc] = rb;
            __syncthreads();
        }
    }

    // ---- epilogue ----
    const int col = n0 + ty * 8;
    const bool ok0 = (!NB) || (col + 4 <= ldn);
    const bool ok1 = (!NB) || (col + 8 <= ldn);
    #pragma unroll
    for (int rp = 0; rp < 4; rp++){
        float v0[8], v1[8];
        #pragma unroll
        for (int c = 0; c < 8; c++) unpack2(acc[rp][c], v0[c], v1[c]);
        #pragma unroll
        for (int half = 0; half < 2; half++){
            float* vv = half ? v1 : v0;
            int r = row0 + tx*8 + rp*2 + half;
            if (ADDX){
                float4 xa = *(const float4*)(a.X + (size_t)r*64 + ty*8);
                float4 xb = *(const float4*)(a.X + (size_t)r*64 + ty*8 + 4);
                vv[0]+=xa.x; vv[1]+=xa.y; vv[2]+=xa.z; vv[3]+=xa.w;
                vv[4]+=xb.x; vv[5]+=xb.y; vv[6]+=xb.z; vv[7]+=xb.w;
            }
            if (SPIKE){
                #pragma unroll
                for (int c = 0; c < 8; c++) vv[c] = spikef(vv[c]);
            }
            if (ok0)
                *(float4*)(a.C + (size_t)r*ldn + col) = make_float4(vv[0],vv[1],vv[2],vv[3]);
            if (ok1)
                *(float4*)(a.C + (size_t)r*ldn + col + 4) = make_float4(vv[4],vv[5],vv[6],vv[7]);
            if (C2W){
                if (ok0)
                    *(float4*)(a.C2 + (size_t)r*ldn + col) = make_float4(vv[0],vv[1],vv[2],vv[3]);
                if (ok1)
                    *(float4*)(a.C2 + (size_t)r*ldn + col + 4) = make_float4(vv[4],vv[5],vv[6],vv[7]);
            }
        }
    }
}

// ------------------------- combine 6 partials -------------------------
struct CB { const float* p[6]; float* dst; const float* cs; const float* cb; };
struct CB2 { CB c[2]; };

template<bool SPIKE, bool COLS>
__global__ void __launch_bounds__(256) combine6(CB2 P){
    const CB c = P.c[blockIdx.y];
    const int idx = (blockIdx.x * 256 + threadIdx.x) * 4;
    float v0 = 0.f, v1 = 0.f, v2 = 0.f, v3 = 0.f;
    #pragma unroll
    for (int s = 0; s < 6; s++){
        float4 a = *(const float4*)(c.p[s] + idx);
        v0 += a.x; v1 += a.y; v2 += a.z; v3 += a.w;
    }
    if (COLS){
        int col = idx & 63;
        float4 cs4 = *(const float4*)(c.cs + col);
        float cb = c.cb[0];
        v0 += cb*cs4.x; v1 += cb*cs4.y; v2 += cb*cs4.z; v3 += cb*cs4.w;
    }
    if (SPIKE){ v0=spikef(v0); v1=spikef(v1); v2=spikef(v2); v3=spikef(v3); }
    *(float4*)(c.dst + idx) = make_float4(v0,v1,v2,v3);
}

// ------------------------- column sums of fe -------------------------
__global__ void __launch_bounds__(256) colsum_kernel(){
    int c = blockIdx.x, om = blockIdx.y;
    float s = 0.f;
    for (int r = threadIdx.x; r < NR; r += 256) s += g_fe[om][(size_t)r*64 + c];
    __shared__ float red[256];
    red[threadIdx.x] = s;
    __syncthreads();
    for (int o = 128; o > 0; o >>= 1){
        if (threadIdx.x < o) red[threadIdx.x] += red[threadIdx.x + o];
        __syncthreads();
    }
    if (threadIdx.x == 0) g_cs[om][c] = red[0];
}

// ------------------------- partial kv -------------------------
__global__ void __launch_bounds__(512) kvpart_kernel(){
    int om = blockIdx.y, bx = blockIdx.x;
    int tid = threadIdx.x;
    int h = tid >> 6, d = (tid >> 3) & 7, e = tid & 7;
    __shared__ float ks[8][64], vs[8][64];
    int r0 = bx * 128;
    int lr = tid >> 6, lc = tid & 63;
    float acc = 0.f;
    for (int c = 0; c < 16; c++){
        ks[lr][lc] = g_k[om][(size_t)(r0 + c*8 + lr)*64 + lc];
        vs[lr][lc] = g_v[om][(size_t)(r0 + c*8 + lr)*64 + lc];
        __syncthreads();
        #pragma unroll
        for (int n = 0; n < 8; n++)
            acc += ks[n][h*8 + d] * vs[n][h*8 + e];
        __syncthreads();
    }
    g_kvp[om][bx][tid] = acc;
}

// ------------------------- reduce kv, build M -------------------------
__global__ void __launch_bounds__(512) kvm_kernel(const float* wp0, const float* wp1){
    int om = blockIdx.x;
    const float* wp = om ? wp1 : wp0;
    int tid = threadIdx.x;
    __shared__ float kvs[512];
    float s = 0.f;
    for (int b = 0; b < 48; b++) s += g_kvp[om][b][tid];
    kvs[tid] = s;
    __syncthreads();
    #pragma unroll
    for (int i = 0; i < 8; i++){
        int idx = tid + i*512;
        int hd = idx >> 6, c = idx & 63;
        int h = hd >> 3, dd = hd & 7;
        float m = 0.f;
        #pragma unroll
        for (int e = 0; e < 8; e++)
            m += kvs[h*64 + dd*8 + e] * wp[(h*8 + e)*64 + c];
        g_M[om][idx] = 0.25f * m;
    }
}

// ------------------------- fused MLP -------------------------
__global__ void __launch_bounds__(256) fc_kernel(const float* fc1w, const float* fc1b,
                                                 const float* fc2w, const float* fc2b,
                                                 float* out3){
    __shared__ float cat_s[64][129];
    int tid = threadIdx.x;
    int row0 = blockIdx.x * 64;
    int tx = tid & 15, ty = tid >> 4;

    for (int i = tid; i < 64*128; i += 256){
        int row = i >> 7, k = i & 127;
        float v = (k < 64) ? g_emb[0][(size_t)(row0+row)*64 + k]
                           : g_emb[1][(size_t)(row0+row)*64 + (k - 64)];
        cat_s[row][k] = v;
    }
    __syncthreads();

    float acc[4][4];
    #pragma unroll
    for (int i = 0; i < 4; i++)
        #pragma unroll
        for (int j = 0; j < 4; j++) acc[i][j] = 0.f;

    for (int k = 0; k < 128; k++){
        float aa[4], bb[4];
        #pragma unroll
        for (int i = 0; i < 4; i++) aa[i] = cat_s[tx*4 + i][k];
        #pragma unroll
        for (int j = 0; j < 4; j++) bb[j] = fc1w[k*64 + ty*4 + j];
        #pragma unroll
        for (int i = 0; i < 4; i++)
            #pragma unroll
            for (int j = 0; j < 4; j++) acc[i][j] += aa[i]*bb[j];
    }
    __syncthreads();
    #pragma unroll
    for (int i = 0; i < 4; i++)
        #pragma unroll
        for (int j = 0; j < 4; j++)
            cat_s[tx*4 + i][ty*4 + j] = spikef(acc[i][j] + fc1b[ty*4 + j]);
    __syncthreads();

    float acc2[4][4];
    #pragma unroll
    for (int i = 0; i < 4; i++)
        #pragma unroll
        for (int j = 0; j < 4; j++) acc2[i][j] = 0.f;
    for (int k = 0; k < 64; k++){
        float aa[4], bb[4];
        #pragma unroll
        for (int i = 0; i < 4; i++) aa[i] = cat_s[tx*4 + i][k];
        #pragma unroll
        for (int j = 0; j < 4; j++) bb[j] = fc2w[k*64 + ty*4 + j];
        #pragma unroll
        for (int i = 0; i < 4; i++)
            #pragma unroll
            for (int j = 0; j < 4; j++) acc2[i][j] += aa[i]*bb[j];
    }
    #pragma unroll
    for (int i = 0; i < 4; i++)
        #pragma unroll
        for (int j = 0; j < 4; j++){
            int r = row0 + tx*4 + i, c = ty*4 + j;
            float v = acc2[i][j] + fc2b[c];
            g_comb[(size_t)r*64 + c] = v;
            out3[(size_t)r*64 + c]   = spikef(v);
        }
}

// ------------------------- launch -------------------------
static inline KA mkKA(const float* A0, const float* A1, const float* B, const float* X,
                      float* C, float* C2, const float* cw, int K, int lda, int ldn){
    KA a; a.A0=A0; a.A1=A1; a.B=B; a.X=X; a.C=C; a.C2=C2;
    a.cw=cw; a.K=K; a.lda=lda; a.ldn=ldn; return a;
}

extern "C" void kernel_launch(void* const* d_in, const int* in_sizes, int n_in,
                              void* d_out, int out_size){
    const float* feat1 = (const float*)d_in[0];
    const float* feat2 = (const float*)d_in[1];
    const float* AS1   = (const float*)d_in[2];
    const float* AF1   = (const float*)d_in[3];
    const float* AS2   = (const float*)d_in[4];
    const float* AF2   = (const float*)d_in[5];
    const float* c1w   = (const float*)d_in[6];
    const float* c1b   = (const float*)d_in[7];
    const float* c2w   = (const float*)d_in[8];
    const float* c2b   = (const float*)d_in[9];
    const float* wenc1 = (const float*)d_in[10];
    const float* wq1   = (const float*)d_in[11];
    const float* wk1   = (const float*)d_in[12];
    const float* wv1   = (const float*)d_in[13];
    const float* wp1   = (const float*)d_in[14];
    const float* wenc2 = (const float*)d_in[15];
    const float* wq2   = (const float*)d_in[16];
    const float* wk2   = (const float*)d_in[17];
    const float* wv2   = (const float*)d_in[18];
    const float* wp2   = (const float*)d_in[19];
    const float* fc1w  = (const float*)d_in[20];
    const float* fc1b  = (const float*)d_in[21];
    const float* fc2w  = (const float*)d_in[22];
    const float* fc2b  = (const float*)d_in[23];
    const float* wdec1 = (const float*)d_in[24];
    const float* wdec2 = (const float*)d_in[25];
    float* out = (float*)d_out;

    float *p_fe, *p_cs, *p_x, *p_q, *p_k, *p_v, *p_M, *p_emb, *p_comb, *p_u, *p_p;
    cudaGetSymbolAddress((void**)&p_fe,  g_fe);
    cudaGetSymbolAddress((void**)&p_cs,  g_cs);
    cudaGetSymbolAddress((void**)&p_x,   g_x);
    cudaGetSymbolAddress((void**)&p_q,   g_q);
    cudaGetSymbolAddress((void**)&p_k,   g_k);
    cudaGetSymbolAddress((void**)&p_v,   g_v);
    cudaGetSymbolAddress((void**)&p_M,   g_M);
    cudaGetSymbolAddress((void**)&p_emb, g_emb);
    cudaGetSymbolAddress((void**)&p_comb,g_comb);
    cudaGetSymbolAddress((void**)&p_u,   g_u);
    cudaGetSymbolAddress((void**)&p_p,   g_p);
    const int OFF = NR*64;
    #define PP(s, om) (p_p + ((s)*2 + (om))*(size_t)OFF)

    KA12 P;
    CB2 C2;

    // 1. fe partials: feat @ w_enc, K-split x6 (all slices %8==0)
    {
        const int off1[7] = {0, 504, 1008, 1512, 2016, 2520, 3000};
        const int off2[7] = {0, 88, 176, 264, 352, 440, 512};
        for (int s = 0; s < 6; s++){
            P.a[s]     = mkKA(feat1 + off1[s], 0, wenc1 + off1[s]*64, 0, PP(s,0), 0, 0,
                              off1[s+1]-off1[s], 3000, 64);
            P.a[6 + s] = mkKA(feat2 + off2[s], 0, wenc2 + off2[s]*64, 0, PP(s,1), 0, 0,
                              off2[s+1]-off2[s], 512, 64);
        }
        gemm8<false,false,false,false,false><<<dim3(48,1,12), 128>>>(P);
    }
    for (int om = 0; om < 2; om++){
        for (int s = 0; s < 6; s++) C2.c[om].p[s] = PP(s,om);
        C2.c[om].dst = p_fe + om*OFF; C2.c[om].cs = 0; C2.c[om].cb = 0;
    }
    combine6<false,false><<<dim3(384,2), 256>>>(C2);

    // 2. column sums of fe
    colsum_kernel<<<dim3(64, 2), 256>>>();

    // 3. x partials: (w0*AS + w1*AF) @ fe, K-split x6
    for (int s = 0; s < 6; s++){
        int k0 = s * 1024;
        P.a[s]     = mkKA(AS1 + k0, AF1 + k0, p_fe + k0*64,       0, PP(s,0), 0, c1w, 1024, NR, 64);
        P.a[6 + s] = mkKA(AS2 + k0, AF2 + k0, p_fe + OFF + k0*64, 0, PP(s,1), 0, c2w, 1024, NR, 64);
    }
    gemm8<true,false,false,false,false><<<dim3(48,1,12), 128>>>(P);

    for (int om = 0; om < 2; om++){
        for (int s = 0; s < 6; s++) C2.c[om].p[s] = PP(s,om);
        C2.c[om].dst = p_x + om*OFF;
        C2.c[om].cs = p_cs + om*64;
        C2.c[om].cb = om ? c2b : c1b;
    }
    combine6<true,true><<<dim3(384,2), 256>>>(C2);

    // 4. q,k,v = spike(x @ w) — six GEMMs, one launch
    P.a[0] = mkKA(p_x,       0, wq1, 0, p_q,       0, 0, 64, 64, 64);
    P.a[1] = mkKA(p_x + OFF, 0, wq2, 0, p_q + OFF, 0, 0, 64, 64, 64);
    P.a[2] = mkKA(p_x,       0, wk1, 0, p_k,       0, 0, 64, 64, 64);
    P.a[3] = mkKA(p_x + OFF, 0, wk2, 0, p_k + OFF, 0, 0, 64, 64, 64);
    P.a[4] = mkKA(p_x,       0, wv1, 0, p_v,       0, 0, 64, 64, 64);
    P.a[5] = mkKA(p_x + OFF, 0, wv2, 0, p_v + OFF, 0, 0, 64, 64, 64);
    for (int i = 6; i < 12; i++) P.a[i] = P.a[0];
    gemm8<false,true,false,false,false><<<dim3(48,1,6), 128>>>(P);

    // 5-6. kv partials, reduce + fold wp into M
    kvpart_kernel<<<dim3(48, 2), 512>>>();
    kvm_kernel<<<2, 512>>>(wp1, wp2);

    // 7. emb = x + q @ M  (writes g_emb and emb1/emb2 outputs)
    P.a[0] = mkKA(p_q,       0, p_M,        p_x,       p_emb,       out,       0, 64, 64, 64);
    P.a[1] = mkKA(p_q + OFF, 0, p_M + 4096, p_x + OFF, p_emb + OFF, out + OFF, 0, 64, 64, 64);
    for (int i = 2; i < 12; i++) P.a[i] = P.a[0];
    gemm8<false,false,true,true,false><<<dim3(48,1,2), 128>>>(P);

    // 8. MLP
    fc_kernel<<<96, 256>>>(fc1w, fc1b, fc2w, fc2b, out + 2*OFF);

    // 9. u partials: AS @ comb, K-split x6
    for (int s = 0; s < 6; s++){
        int k0 = s * 1024;
        P.a[s]     = mkKA(AS1 + k0, 0, p_comb + k0*64, 0, PP(s,0), 0, 0, 1024, NR, 64);
        P.a[6 + s] = mkKA(AS2 + k0, 0, p_comb + k0*64, 0, PP(s,1), 0, 0, 1024, NR, 64);
    }
    gemm8<false,false,false,false,false><<<dim3(48,1,12), 128>>>(P);

    for (int om = 0; om < 2; om++){
        for (int s = 0; s < 6; s++) C2.c[om].p[s] = PP(s,om);
        C2.c[om].dst = p_u + om*OFF; C2.c[om].cs = 0; C2.c[om].cb = 0;
    }
    combine6<false,false><<<dim3(384,2), 256>>>(C2);

    // 10. recon = spike(u @ w_dec) (N-tiled)
    P.a[0] = mkKA(p_u, 0, wdec1, 0, out + 3*(size_t)OFF, 0, 0, 64, 64, 3000);
    for (int i = 1; i < 12; i++) P.a[i] = P.a[0];
    gemm8<false,true,false,false,true><<<dim3(48,47,1), 128>>>(P);

    P.a[0] = mkKA(p_u + OFF, 0, wdec2, 0, out + 3*(size_t)OFF + (size_t)NR*3000,
                  0, 0, 64, 64, 512);
    for (int i = 1; i < 12; i++) P.a[i] = P.a[0];
    gemm8<false,true,false,false,true><<<dim3(48,8,1), 128>>>(P);
}